// round 10
// baseline (speedup 1.0000x reference)
#include <cuda_runtime.h>
#include <math.h>

#define NB    256
#define TP    32
#define TFUT  256
#define HH    100
#define NF    275
#define HGG   75
#define HOO   75
#define NTHR  288
#define NCTA  128

// ---- transposed weights in global scratch ----
// g_W13T: [0,27775) W1T[k*275+n]; [27775] pad; [27776,55376) W3T[k*100+n] (276 rows, row 275 = 0)
__device__ __align__(16) float g_W13T[55376];
__device__ __align__(16) float g_W2T[276 * 276];   // W2T[k*276+n]; col 275 = 0, row 275 = 0
__device__ __align__(16) float g_WhhT[100 * 300];
__device__ __align__(16) float g_oW1T[100 * 75];
__device__ __align__(16) float g_oW2T[75 * 75];
__device__ float g_hB[NB * HH];
__device__ float g_gx[NB * 2];
__device__ float g_z0[NB * HH];

// ---- shared layout (float offsets), total 57636 floats = 230,544 B ----
#define OFF_W1T  0        // 27775 + 1 pad
#define OFF_W3T  27776    // 276*100 = 27600
#define OFF_IN   55376    // float2[102]
#define OFF_HID  55580    // float2[276]
#define OFF_A2   56132    // float2[276]
#define OFF_Y    56684    // float2[100]
#define OFF_KS   56884    // float2[100]
#define OFF_PART 57084    // float4[138]
#define SMEM_BYTES (57636 * 4)

__device__ __forceinline__ float leaky1(float x) {
    const float SL = 1.0f / 5.5f;
    return x >= 0.f ? x : x * SL;
}
__device__ __forceinline__ float sigm1(float x) { return 1.f / (1.f + expf(-x)); }

// ---- W2 stream/consume macros (16-row chunks, 2 outputs per thread) ----
#define W2_REFILL(R, ROW0)                                                    \
    _Pragma("unroll")                                                         \
    for (int i_ = 0; i_ < 16; i_++)                                           \
        R[i_] = __ldcg((const float2*)(p + ((ROW0) + i_) * 276));

#define W2_CONS(W, C) {                                                       \
    const float4* xx_ = (const float4*)(x2 + (C) * 16);                       \
    _Pragma("unroll")                                                         \
    for (int ii_ = 0; ii_ < 8; ii_++) {                                       \
        float4 xv_ = xx_[ii_];                                                \
        ac.x = fmaf((W)[2*ii_].x,   xv_.x, ac.x);                             \
        ac.y = fmaf((W)[2*ii_].x,   xv_.y, ac.y);                             \
        ac.z = fmaf((W)[2*ii_].y,   xv_.x, ac.z);                             \
        ac.w = fmaf((W)[2*ii_].y,   xv_.y, ac.w);                             \
        bc.x = fmaf((W)[2*ii_+1].x, xv_.z, bc.x);                             \
        bc.y = fmaf((W)[2*ii_+1].x, xv_.w, bc.y);                             \
        bc.z = fmaf((W)[2*ii_+1].y, xv_.z, bc.z);                             \
        bc.w = fmaf((W)[2*ii_+1].y, xv_.w, bc.w);                             \
    } }

// W2 register cache: rows k=0..47 (chunks 0..2) + tail rows k=128..137.
#define W2C_ROWS 58

// ---- Layer-3 partial: output n, NK=138, W3T in SMEM (stride 100, lane-coalesced). ----
__device__ __forceinline__ float2 dotW3(const float* __restrict__ w,
                                        const float2* __restrict__ x2) {
    float a0 = 0.f, a1 = 0.f, b0 = 0.f, b1 = 0.f;
#pragma unroll
    for (int c = 0; c < 17; c++) {
        float wr[8]; float2 xr[8];
#pragma unroll
        for (int i = 0; i < 8; i++) { wr[i] = w[(c * 8 + i) * 100]; xr[i] = x2[c * 8 + i]; }
#pragma unroll
        for (int i = 0; i < 8; i += 2) {
            a0 = fmaf(wr[i],     xr[i].x,     a0); a1 = fmaf(wr[i],     xr[i].y,     a1);
            b0 = fmaf(wr[i + 1], xr[i + 1].x, b0); b1 = fmaf(wr[i + 1], xr[i + 1].y, b1);
        }
    }
#pragma unroll
    for (int i = 136; i < 138; i++) {
        float wv = w[i * 100]; float2 x = x2[i];
        a0 = fmaf(wv, x.x, a0); a1 = fmaf(wv, x.y, a1);
    }
    return make_float2(a0 + b0, a1 + b1);
}

// ---- One RK4 stage: field MLP on s_in, fused stage update. Ends synced. ----
__device__ __forceinline__ void field_stage(int tid, float* sm, int stage,
        float2 dt, float2 tnext, bool write_in, const float2* __restrict__ wc,
        float rb1, float rb2a, float rb2b, float rb3) {
    float2* s_in  = (float2*)(sm + OFF_IN);
    float2* s_hid = (float2*)(sm + OFF_HID);
    float2* s_a2  = (float2*)(sm + OFF_A2);
    float2* s_y   = (float2*)(sm + OFF_Y);
    float2* s_ks  = (float2*)(sm + OFF_KS);
    float4* s_p4  = (float4*)(sm + OFF_PART);
    float2* s_p2  = (float2*)(sm + OFF_PART);

    // L1: 101 -> 275 (W1T in smem)
    if (tid < NF) {
        const float* w = sm + OFF_W1T + tid;
        const float2* x2 = (const float2*)(sm + OFF_IN);
        float a0 = rb1, a1 = rb1, b0 = 0.f, b1 = 0.f, c0 = 0.f, c1 = 0.f, d0 = 0.f, d1 = 0.f;
#pragma unroll
        for (int c = 0; c < 12; c++) {
            float wr[8]; float2 xr[8];
#pragma unroll
            for (int i = 0; i < 8; i++) { wr[i] = w[(c * 8 + i) * 275]; xr[i] = x2[c * 8 + i]; }
#pragma unroll
            for (int i = 0; i < 8; i += 4) {
                a0 = fmaf(wr[i],     xr[i].x,     a0); a1 = fmaf(wr[i],     xr[i].y,     a1);
                b0 = fmaf(wr[i + 1], xr[i + 1].x, b0); b1 = fmaf(wr[i + 1], xr[i + 1].y, b1);
                c0 = fmaf(wr[i + 2], xr[i + 2].x, c0); c1 = fmaf(wr[i + 2], xr[i + 2].y, c1);
                d0 = fmaf(wr[i + 3], xr[i + 3].x, d0); d1 = fmaf(wr[i + 3], xr[i + 3].y, d1);
            }
        }
#pragma unroll
        for (int i = 96; i < 101; i++) {
            float wv = w[i * 275]; float2 x = x2[i];
            a0 = fmaf(wv, x.x, a0); a1 = fmaf(wv, x.y, a1);
        }
        s_hid[tid] = make_float2(tanhf((a0 + b0) + (c0 + d0)),
                                 tanhf((a1 + b1) + (c1 + d1)));
    }
    __syncthreads();

    // L2: 275 -> 275; k rows 0..47 + 128..137 from register cache, rows 48..127
    // streamed double-buffered. k-split over 2 groups of 138 threads.
    int g = tid / 144, j = tid - g * 144;
    bool act = (j < 138);
    int n0 = 2 * j;
    float4 acc;
    if (act) {
        const float* p = g_W2T + (g * 138) * 276 + n0;
        const float2* x2 = ((const float2*)(sm + OFF_HID)) + g * 138;
        float4 ac = make_float4(0.f, 0.f, 0.f, 0.f);
        float4 bc = make_float4(0.f, 0.f, 0.f, 0.f);
        float2 u[16], v[16];
        W2_REFILL(u, 48)
        W2_REFILL(v, 64)
        W2_CONS(wc, 0)
        W2_CONS((wc + 16), 1)
        W2_CONS((wc + 32), 2)
        W2_CONS(u, 3) W2_REFILL(u, 80)
        W2_CONS(v, 4) W2_REFILL(v, 96)
        W2_CONS(u, 5) W2_REFILL(u, 112)
        W2_CONS(v, 6)
        W2_CONS(u, 7)
#pragma unroll
        for (int i = 0; i < 10; i++) {       // cached tail k = 128..137
            float2 wv = wc[48 + i];
            float2 xv = x2[128 + i];
            if (i & 1) {
                bc.x = fmaf(wv.x, xv.x, bc.x); bc.y = fmaf(wv.x, xv.y, bc.y);
                bc.z = fmaf(wv.y, xv.x, bc.z); bc.w = fmaf(wv.y, xv.y, bc.w);
            } else {
                ac.x = fmaf(wv.x, xv.x, ac.x); ac.y = fmaf(wv.x, xv.y, ac.y);
                ac.z = fmaf(wv.y, xv.x, ac.z); ac.w = fmaf(wv.y, xv.y, ac.w);
            }
        }
        acc = make_float4(ac.x + bc.x, ac.y + bc.y, ac.z + bc.z, ac.w + bc.w);
        if (g) s_p4[j] = acc;
    }
    __syncthreads();
    if (act && !g) {
        float4 pp = s_p4[j];
        s_a2[n0]     = make_float2(tanhf(acc.x + pp.x + rb2a), tanhf(acc.y + pp.y + rb2a));
        s_a2[n0 + 1] = make_float2(tanhf(acc.z + pp.z + rb2b), tanhf(acc.w + pp.w + rb2b));
    }
    __syncthreads();

    // L3: 275 -> 100 (W3T in smem, k-split, both NK=138 via zero row), fused update
    float2 a3 = make_float2(0.f, 0.f);
    if (tid < 100) {
        a3 = dotW3(sm + OFF_W3T + tid, (const float2*)(sm + OFF_A2));
    } else if (tid < 200) {
        s_p2[tid - 100] = dotW3(sm + OFF_W3T + 138 * 100 + (tid - 100),
                                ((const float2*)(sm + OFF_A2)) + 138);
    }
    __syncthreads();
    if (tid < 100) {
        float2 pp = s_p2[tid];
        float2 f = make_float2(tanhf(a3.x + pp.x + rb3), tanhf(a3.y + pp.y + rb3));
        float2 y = s_y[tid];
        if (stage == 0) {
            s_ks[tid] = f;
            s_in[1 + tid] = make_float2(fmaf(0.5f * dt.x, f.x, y.x),
                                        fmaf(0.5f * dt.y, f.y, y.y));
        } else if (stage == 1) {
            float2 k = s_ks[tid];
            s_ks[tid] = make_float2(k.x + 2.f * f.x, k.y + 2.f * f.y);
            s_in[1 + tid] = make_float2(fmaf(0.5f * dt.x, f.x, y.x),
                                        fmaf(0.5f * dt.y, f.y, y.y));
        } else if (stage == 2) {
            float2 k = s_ks[tid];
            s_ks[tid] = make_float2(k.x + 2.f * f.x, k.y + 2.f * f.y);
            s_in[1 + tid] = make_float2(fmaf(dt.x, f.x, y.x),
                                        fmaf(dt.y, f.y, y.y));
        } else {
            float2 k = s_ks[tid];
            float2 yn = make_float2(y.x + dt.x * (k.x + f.x) / 6.f,
                                    y.y + dt.y * (k.y + f.y) / 6.f);
            s_y[tid] = yn;
            if (write_in) s_in[1 + tid] = yn;
        }
        if (tid == 0 && (stage < 3 || write_in)) s_in[0] = tnext;
    }
    __syncthreads();
}

// ---- RK4, NSUB=2 ----
__device__ __forceinline__ void integrate2(int tid, float* sm, float2 t0, float2 t1,
        const float2* __restrict__ wc,
        float rb1, float rb2a, float rb2b, float rb3) {
    float2* s_in = (float2*)(sm + OFF_IN);
    float2* s_y  = (float2*)(sm + OFF_Y);
    float2 dt = make_float2((t1.x - t0.x) * 0.5f, (t1.y - t0.y) * 0.5f);
    if (tid < HH) s_in[1 + tid] = s_y[tid];
    if (tid == 0) s_in[0] = t0;
    __syncthreads();
#pragma unroll 1
    for (int st = 0; st < 8; st++) {
        int stage = st & 3, sub = st >> 2;
        float2 tb = make_float2(t0.x + sub * dt.x, t0.y + sub * dt.y);
        float2 tnext = (stage <= 1)
            ? make_float2(tb.x + 0.5f * dt.x, tb.y + 0.5f * dt.y)
            : make_float2(tb.x + dt.x, tb.y + dt.y);
        field_stage(tid, sm, stage, dt, tnext, (st == 3), wc, rb1, rb2a, rb2b, rb3);
    }
}

// ---- load the per-thread W2 register cache (rows 0..47 + 128..137 of this slice) ----
#define W2C_LOAD(wc, tid)                                                     \
    {                                                                         \
        int g_ = (tid) / 144, j_ = (tid) - g_ * 144;                          \
        if (j_ < 138) {                                                       \
            const float* pc_ = g_W2T + (g_ * 138) * 276 + 2 * j_;             \
            _Pragma("unroll")                                                 \
            for (int i_ = 0; i_ < 48; i_++)                                   \
                wc[i_] = __ldg((const float2*)(pc_ + i_ * 276));              \
            _Pragma("unroll")                                                 \
            for (int i_ = 0; i_ < 10; i_++)                                   \
                wc[48 + i_] = __ldg((const float2*)(pc_ + (128 + i_) * 276)); \
        } else {                                                              \
            _Pragma("unroll")                                                 \
            for (int i_ = 0; i_ < W2C_ROWS; i_++)                             \
                wc[i_] = make_float2(0.f, 0.f);                               \
        }                                                                     \
    }

// ---- prep: build transposed weight copies (with zero-pad rows) ----
__global__ void prep_kernel(const float* __restrict__ fW1, const float* __restrict__ fW2,
                            const float* __restrict__ fW3, const float* __restrict__ Whh,
                            const float* __restrict__ oW1, const float* __restrict__ oW2) {
    for (int i = blockIdx.x * blockDim.x + threadIdx.x; i < 174677;
         i += gridDim.x * blockDim.x) {
        if (i < 55376) {
            if (i < 27775) {
                int n = i % 275, k = i / 275;
                g_W13T[i] = fW1[n * 101 + k];
            } else if (i == 27775) {
                g_W13T[i] = 0.f;
            } else {
                int j = i - 27776, k = j / 100, n = j % 100;
                g_W13T[i] = (k < 275) ? fW3[n * 275 + k] : 0.f;
            }
        } else if (i < 131552) {
            int j = i - 55376, k = j / 276, n = j % 276;
            g_W2T[j] = (n < 275 && k < 275) ? fW2[n * 275 + k] : 0.f;
        } else if (i < 161552) {
            int j = i - 131552, k = j / 300, n = j % 300;
            g_WhhT[j] = Whh[n * 100 + k];
        } else if (i < 169052) {
            int j = i - 161552, k = j / 75, n = j % 75;
            g_oW1T[j] = oW1[n * 100 + k];
        } else {
            int j = i - 169052, k = j / 75, n = j % 75;
            g_oW2T[j] = oW2[n * 75 + k];
        }
    }
}

// ---- encode ----
__global__ void __launch_bounds__(NTHR, 1) encode_kernel(
        const float* __restrict__ past, const float* __restrict__ h0,
        const float* __restrict__ fb1, const float* __restrict__ fb2,
        const float* __restrict__ fb3,
        const float* __restrict__ Wih, const float* __restrict__ bih,
        const float* __restrict__ bhh) {
    extern __shared__ float sm[];
    int tid = threadIdx.x;
    int r0 = blockIdx.x * 2, r1 = r0 + 1;

    const float4* src = (const float4*)g_W13T;
    float4* dst = (float4*)sm;
    for (int i = tid; i < 55376 / 4; i += NTHR) dst[i] = src[i];

    float2 wc[W2C_ROWS];
    W2C_LOAD(wc, tid)

    float rb1 = (tid < NF) ? __ldg(fb1 + tid) : 0.f;
    int g = tid / 144, j = tid - g * 144;
    float rb2a = 0.f, rb2b = 0.f;
    if (g == 0 && j < 138) {
        rb2a = __ldg(fb2 + 2 * j);
        rb2b = (2 * j + 1 < NF) ? __ldg(fb2 + 2 * j + 1) : 0.f;
    }
    float rb3 = (tid < HH) ? __ldg(fb3 + tid) : 0.f;

    float2* s_y   = (float2*)(sm + OFF_Y);
    float2* s_u   = (float2*)(sm + OFF_HID);   // [200] aliased
    float2* s_inn = (float2*)(sm + OFF_A2);    // [100]
    float2* s_hn  = (float2*)(sm + OFF_PART);  // [100]
    if (tid < HH) s_y[tid] = make_float2(h0[r0 * HH + tid], h0[r1 * HH + tid]);
    if (tid == 0) ((float2*)(sm + OFF_HID))[275] = make_float2(0.f, 0.f);
    __syncthreads();

    float2 tprev = make_float2(0.f, 0.f);
    for (int step = 0; step < TP; step++) {
        float2 tcur = make_float2(past[(r0 * TP + step) * 2], past[(r1 * TP + step) * 2]);
        float2 t0 = (step == 0) ? make_float2(tcur.x - 1.f, tcur.y - 1.f) : tprev;
        integrate2(tid, sm, t0, tcur, wc, rb1, rb2a, rb2b, rb3);

        float2 x = make_float2(past[(r0 * TP + step) * 2 + 1],
                               past[(r1 * TP + step) * 2 + 1]);
        const float4* y4 = (const float4*)(sm + OFF_Y);
        for (int jj = tid; jj < 300; jj += NTHR) {
            float bh = __ldg(bhh + jj);
            float a0 = bh, a1 = bh, b0 = 0.f, b1 = 0.f;
#pragma unroll 10
            for (int k = 0; k < 100; k += 2) {
                float w0 = __ldcg(g_WhhT + k * 300 + jj);
                float w1 = __ldcg(g_WhhT + (k + 1) * 300 + jj);
                float4 y = y4[k >> 1];
                a0 = fmaf(w0, y.x, a0); a1 = fmaf(w0, y.y, a1);
                b0 = fmaf(w1, y.z, b0); b1 = fmaf(w1, y.w, b1);
            }
            a0 += b0; a1 += b1;
            float wi = __ldg(Wih + jj), bi = __ldg(bih + jj);
            float2 gi = make_float2(fmaf(wi, x.x, bi), fmaf(wi, x.y, bi));
            if (jj < 200) s_u[jj] = make_float2(gi.x + a0, gi.y + a1);
            else { s_inn[jj - 200] = gi; s_hn[jj - 200] = make_float2(a0, a1); }
        }
        __syncthreads();
        if (tid < HH) {
            float2 u1 = s_u[tid], u2 = s_u[HH + tid];
            float2 gin = s_inn[tid], ghn = s_hn[tid], h = s_y[tid];
            float rx = sigm1(u1.x), ry = sigm1(u1.y);
            float zx = sigm1(u2.x), zy = sigm1(u2.y);
            float nx = tanhf(gin.x + rx * ghn.x), ny = tanhf(gin.y + ry * ghn.y);
            s_y[tid] = make_float2((1.f - zx) * nx + zx * h.x,
                                   (1.f - zy) * ny + zy * h.y);
        }
        __syncthreads();
        tprev = tcur;
    }
    if (tid < HH) {
        g_hB[r0 * HH + tid] = s_y[tid].x;
        g_hB[r1 * HH + tid] = s_y[tid].y;
    }
}

// ---- decoder head ----
__global__ void gx_kernel(const float* __restrict__ gW1, const float* __restrict__ gb1,
                          const float* __restrict__ gW2, const float* __restrict__ gb2,
                          const float* __restrict__ gW3, const float* __restrict__ gb3) {
    int b = blockIdx.x, tid = threadIdx.x;
    __shared__ float sh[HH], s1[HGG], s2[HGG];
    for (int k = tid; k < HH; k += blockDim.x) sh[k] = g_hB[b * HH + k];
    __syncthreads();
    if (tid < HGG) {
        float a = __ldg(gb1 + tid);
        const float* w = gW1 + tid * HH;
        for (int k = 0; k < HH; k++) a = fmaf(__ldg(w + k), sh[k], a);
        s1[tid] = leaky1(a);
    }
    __syncthreads();
    if (tid < HGG) {
        float a = __ldg(gb2 + tid);
        const float* w = gW2 + tid * HGG;
        for (int k = 0; k < HGG; k++) a = fmaf(__ldg(w + k), s1[k], a);
        s2[tid] = leaky1(a);
    }
    __syncthreads();
    if (tid < 2) {
        float a = __ldg(gb3 + tid);
        const float* w = gW3 + tid * HGG;
        for (int k = 0; k < HGG; k++) a = fmaf(__ldg(w + k), s2[k], a);
        g_gx[b * 2 + tid] = a;
    }
}

__global__ void z0_kernel(const float* __restrict__ eps) {
    int b = blockIdx.x, h = threadIdx.x;
    float loc, scale;
    if (b < NB / 2) {
        loc   = g_gx[(2 * b) * 2 + 0];
        scale = g_gx[(2 * b + 1) * 2 + 0];
    } else {
        int i = 2 * (b - NB / 2);
        loc   = fabsf(g_gx[i * 2 + 1]);
        scale = fabsf(g_gx[(i + 1) * 2 + 1]);
    }
    g_z0[b * HH + h] = loc + scale * eps[h * NB + b];
}

// ---- rollout output MLP ----
__device__ __forceinline__ void out_mlp(int tid, int s, int r0, int r1, float* sm,
        float rob1, float rob2,
        const float* __restrict__ oW3, const float* __restrict__ ob3,
        float* __restrict__ out) {
    float2* s_o1 = (float2*)(sm + OFF_HID);
    float2* s_o2 = (float2*)(sm + OFF_A2);
    if (tid < HOO) {
        const float4* y4 = (const float4*)(sm + OFF_Y);
        float a0 = rob1, a1 = rob1, b0 = 0.f, b1 = 0.f;
#pragma unroll 10
        for (int k = 0; k < 100; k += 2) {
            float w0 = __ldcg(g_oW1T + k * 75 + tid);
            float w1 = __ldcg(g_oW1T + (k + 1) * 75 + tid);
            float4 y = y4[k >> 1];
            a0 = fmaf(w0, y.x, a0); a1 = fmaf(w0, y.y, a1);
            b0 = fmaf(w1, y.z, b0); b1 = fmaf(w1, y.w, b1);
        }
        s_o1[tid] = make_float2(leaky1(a0 + b0), leaky1(a1 + b1));
    }
    __syncthreads();
    if (tid < HOO) {
        const float4* h4 = (const float4*)(sm + OFF_HID);
        float a0 = rob2, a1 = rob2, b0 = 0.f, b1 = 0.f;
#pragma unroll 8
        for (int k = 0; k + 1 < HOO; k += 2) {
            float w0 = __ldcg(g_oW2T + k * 75 + tid);
            float w1 = __ldcg(g_oW2T + (k + 1) * 75 + tid);
            float4 h = h4[k >> 1];
            a0 = fmaf(w0, h.x, a0); a1 = fmaf(w0, h.y, a1);
            b0 = fmaf(w1, h.z, b0); b1 = fmaf(w1, h.w, b1);
        }
        {
            float w0 = __ldcg(g_oW2T + 74 * 75 + tid);
            float2 h = s_o1[74];
            a0 = fmaf(w0, h.x, a0); a1 = fmaf(w0, h.y, a1);
        }
        s_o2[tid] = make_float2(leaky1(a0 + b0), leaky1(a1 + b1));
    }
    __syncthreads();
    if (tid < 32) {
        float a0 = 0.f, a1 = 0.f;
        for (int k = tid; k < HOO; k += 32) {
            float wv = __ldg(oW3 + k);
            float2 h = s_o2[k];
            a0 = fmaf(wv, h.x, a0); a1 = fmaf(wv, h.y, a1);
        }
#pragma unroll
        for (int o = 16; o; o >>= 1) {
            a0 += __shfl_down_sync(0xffffffffu, a0, o);
            a1 += __shfl_down_sync(0xffffffffu, a1, o);
        }
        if (tid == 0) {
            float b = __ldg(ob3);
            out[r0 * TFUT + s] = a0 + b;
            out[r1 * TFUT + s] = a1 + b;
        }
    }
    __syncthreads();
}

__global__ void __launch_bounds__(NTHR, 1) rollout_kernel(
        const float* __restrict__ tf_,
        const float* __restrict__ fb1, const float* __restrict__ fb2,
        const float* __restrict__ fb3,
        const float* __restrict__ ob1, const float* __restrict__ ob2,
        const float* __restrict__ oW3, const float* __restrict__ ob3,
        float* __restrict__ out) {
    extern __shared__ float sm[];
    int tid = threadIdx.x;
    int r0 = blockIdx.x * 2, r1 = r0 + 1;

    const float4* src = (const float4*)g_W13T;
    float4* dst = (float4*)sm;
    for (int i = tid; i < 55376 / 4; i += NTHR) dst[i] = src[i];

    float2 wc[W2C_ROWS];
    W2C_LOAD(wc, tid)

    float rb1 = (tid < NF) ? __ldg(fb1 + tid) : 0.f;
    int g = tid / 144, j = tid - g * 144;
    float rb2a = 0.f, rb2b = 0.f;
    if (g == 0 && j < 138) {
        rb2a = __ldg(fb2 + 2 * j);
        rb2b = (2 * j + 1 < NF) ? __ldg(fb2 + 2 * j + 1) : 0.f;
    }
    float rb3 = (tid < HH) ? __ldg(fb3 + tid) : 0.f;
    float rob1 = (tid < HOO) ? __ldg(ob1 + tid) : 0.f;
    float rob2 = (tid < HOO) ? __ldg(ob2 + tid) : 0.f;

    float2* s_y = (float2*)(sm + OFF_Y);
    if (tid < HH) s_y[tid] = make_float2(g_z0[r0 * HH + tid], g_z0[r1 * HH + tid]);
    if (tid == 0) ((float2*)(sm + OFF_HID))[275] = make_float2(0.f, 0.f);
    __syncthreads();

    out_mlp(tid, 0, r0, r1, sm, rob1, rob2, oW3, ob3, out);

    float2 tprev = make_float2(tf_[r0 * TFUT], tf_[r1 * TFUT]);
    for (int s = 1; s < TFUT; s++) {
        float2 tcur = make_float2(tf_[r0 * TFUT + s], tf_[r1 * TFUT + s]);
        integrate2(tid, sm, tprev, tcur, wc, rb1, rb2a, rb2b, rb3);
        out_mlp(tid, s, r0, r1, sm, rob1, rob2, oW3, ob3, out);
        tprev = tcur;
    }
}

extern "C" void kernel_launch(void* const* d_in, const int* in_sizes, int n_in,
                              void* d_out, int out_size) {
    const float* past = (const float*)d_in[0];
    const float* h0   = (const float*)d_in[1];
    const float* t_fu = (const float*)d_in[2];
    const float* eps  = (const float*)d_in[3];
    const float* fW1  = (const float*)d_in[4];
    const float* fb1  = (const float*)d_in[5];
    const float* fW2  = (const float*)d_in[6];
    const float* fb2  = (const float*)d_in[7];
    const float* fW3  = (const float*)d_in[8];
    const float* fb3  = (const float*)d_in[9];
    const float* Wih  = (const float*)d_in[10];
    const float* Whh  = (const float*)d_in[11];
    const float* bih  = (const float*)d_in[12];
    const float* bhh  = (const float*)d_in[13];
    const float* gW1  = (const float*)d_in[14];
    const float* gb1  = (const float*)d_in[15];
    const float* gW2  = (const float*)d_in[16];
    const float* gb2  = (const float*)d_in[17];
    const float* gW3  = (const float*)d_in[18];
    const float* gb3  = (const float*)d_in[19];
    const float* oW1  = (const float*)d_in[20];
    const float* ob1  = (const float*)d_in[21];
    const float* oW2  = (const float*)d_in[22];
    const float* ob2  = (const float*)d_in[23];
    const float* oW3  = (const float*)d_in[24];
    const float* ob3  = (const float*)d_in[25];
    float* out = (float*)d_out;

    static bool attr_done = false;
    if (!attr_done) {
        cudaFuncSetAttribute(encode_kernel,
                             cudaFuncAttributeMaxDynamicSharedMemorySize, SMEM_BYTES);
        cudaFuncSetAttribute(rollout_kernel,
                             cudaFuncAttributeMaxDynamicSharedMemorySize, SMEM_BYTES);
        attr_done = true;
    }

    prep_kernel<<<192, 256>>>(fW1, fW2, fW3, Whh, oW1, oW2);
    encode_kernel<<<NCTA, NTHR, SMEM_BYTES>>>(past, h0, fb1, fb2, fb3, Wih, bih, bhh);
    gx_kernel<<<NB, 96>>>(gW1, gb1, gW2, gb2, gW3, gb3);
    z0_kernel<<<NB, HH>>>(eps);
    rollout_kernel<<<NCTA, NTHR, SMEM_BYTES>>>(t_fu, fb1, fb2, fb3,
                                               ob1, ob2, oW3, ob3, out);
}

// round 11
// speedup vs baseline: 1.3832x; 1.3832x over previous
#include <cuda_runtime.h>
#include <math.h>

#define NB    256
#define TP    32
#define TFUT  256
#define HH    100
#define NF    275
#define HGG   75
#define HOO   75
#define NTHR  288
#define NCTA  128

// ---- transposed/packed weights in global scratch ----
// g_W13P: [0,28050) W1P[(kp*275+n)*2+r] (k=2kp+r); [28050,28052) pad;
//         [28052,55652) W3P[((half*69+kp)*100+n)*2+r] (k=half*138+2kp+r, k=275 -> 0)
__device__ __align__(16) float g_W13P[55652];
__device__ __align__(16) float g_W2T[276 * 276];   // W2T[k*276+n]; col 275 = 0, row 275 = 0
__device__ __align__(16) float g_WhhT[100 * 300];
__device__ __align__(16) float g_oW1T[100 * 75];
__device__ __align__(16) float g_oW2T[75 * 75];
__device__ float g_hB[NB * HH];
__device__ float g_gx[NB * 2];
__device__ float g_z0[NB * HH];

// ---- shared layout (float offsets), total 57912 floats = 231,648 B ----
#define OFF_W1P  0
#define OFF_W3P  28052
#define OFF_IN   55652   // float2[102] (slot 101 = zero pad)
#define OFF_HID  55856   // float2[276] (slot 275 = zero pad)
#define OFF_A2   56408   // float2[276]
#define OFF_Y    56960   // float2[100]
#define OFF_KS   57160   // float2[100] (unused, kept for layout stability)
#define OFF_PART 57360   // float4[138]
#define SMEM_BYTES (57912 * 4)

__device__ __forceinline__ float leaky1(float x) {
    const float SL = 1.0f / 5.5f;
    return x >= 0.f ? x : x * SL;
}
// Fast branch-free tanh: clamp to +-9 (tanh saturates to 1 ulp), exp-based.
__device__ __forceinline__ float ftanh(float x) {
    float xc = fminf(fmaxf(x, -9.f), 9.f);
    float e  = __expf(2.f * xc);
    return __fdividef(e - 1.f, e + 1.f);
}
__device__ __forceinline__ float fsigm(float x) {
    return __fdividef(1.f, 1.f + __expf(-x));
}

// ---- W2 ring-pipeline macros (16-row chunks, float2 = 2 outputs per thread) ----
#define W2_REFILL(R, ROW0)                                                    \
    _Pragma("unroll")                                                         \
    for (int i_ = 0; i_ < 16; i_++)                                           \
        R[i_] = __ldcg((const float2*)(p + ((ROW0) + i_) * 276));

#define W2_CONSUME(R, C) {                                                    \
    const float4* xx_ = (const float4*)(x2 + (C) * 16);                       \
    _Pragma("unroll")                                                         \
    for (int ii_ = 0; ii_ < 8; ii_++) {                                       \
        float4 xv_ = xx_[ii_];                                                \
        ac.x = fmaf(R[2*ii_].x,   xv_.x, ac.x);                               \
        ac.y = fmaf(R[2*ii_].x,   xv_.y, ac.y);                               \
        ac.z = fmaf(R[2*ii_].y,   xv_.x, ac.z);                               \
        ac.w = fmaf(R[2*ii_].y,   xv_.y, ac.w);                               \
        bc.x = fmaf(R[2*ii_+1].x, xv_.z, bc.x);                               \
        bc.y = fmaf(R[2*ii_+1].x, xv_.w, bc.y);                               \
        bc.z = fmaf(R[2*ii_+1].y, xv_.z, bc.z);                               \
        bc.w = fmaf(R[2*ii_+1].y, xv_.w, bc.w);                               \
    } }

// ---- Layer-3 partial: output n, one k-half (69 pairs), W3P in SMEM ----
__device__ __forceinline__ float2 dotW3(const float2* __restrict__ wp,
                                        const float2* __restrict__ x2base) {
    const float4* x4 = (const float4*)x2base;
    float a0 = 0.f, a1 = 0.f, b0 = 0.f, b1 = 0.f;
#pragma unroll
    for (int c = 0; c < 17; c++) {
        float2 wr[4]; float4 xr[4];
#pragma unroll
        for (int i = 0; i < 4; i++) { wr[i] = wp[(c * 4 + i) * 100]; xr[i] = x4[c * 4 + i]; }
#pragma unroll
        for (int i = 0; i < 4; i++) {
            a0 = fmaf(wr[i].x, xr[i].x, a0); a1 = fmaf(wr[i].x, xr[i].y, a1);
            b0 = fmaf(wr[i].y, xr[i].z, b0); b1 = fmaf(wr[i].y, xr[i].w, b1);
        }
    }
    {   // kp = 68
        float2 w = wp[68 * 100]; float4 x = x4[68];
        a0 = fmaf(w.x, x.x, a0); a1 = fmaf(w.x, x.y, a1);
        b0 = fmaf(w.y, x.z, b0); b1 = fmaf(w.y, x.w, b1);
    }
    return make_float2(a0 + b0, a1 + b1);
}

// ---- One RK4 stage: W2 prefetch -> L1 -> L2(pipelined) -> L3 -> fused update ----
// ry/rks are the per-thread (tid<100) RK4 state registers.
__device__ __forceinline__ void field_stage(int tid, float* sm, int stage,
        float2 dt, float2 tnext, bool write_in, bool write_y,
        float2& ry, float2& rks,
        float rb1, float rb2a, float rb2b, float rb3) {
    float2* s_in  = (float2*)(sm + OFF_IN);
    float2* s_hid = (float2*)(sm + OFF_HID);
    float2* s_a2  = (float2*)(sm + OFF_A2);
    float2* s_y   = (float2*)(sm + OFF_Y);
    float4* s_p4  = (float4*)(sm + OFF_PART);
    float2* s_p2  = (float2*)(sm + OFF_PART);

    int g = tid / 144, j = tid - g * 144;
    bool act = (j < 138);
    int n0 = 2 * j;
    const float* p = g_W2T + (g * 138) * 276 + n0;

    // ---- W2 prefetch: rows 0..47 + tail 128..137 issued BEFORE L1 compute ----
    float2 r0[16], r1[16], r2[16], tl[10];
    if (act) {
        W2_REFILL(r0, 0)
        W2_REFILL(r1, 16)
        W2_REFILL(r2, 32)
#pragma unroll
        for (int i = 0; i < 10; i++)
            tl[i] = __ldcg((const float2*)(p + (128 + i) * 276));
    }

    // ---- L1: 101 -> 275 (W1P paired in smem) ----
    if (tid < NF) {
        const float2* wp = ((const float2*)(sm + OFF_W1P)) + tid;
        const float4* x4 = (const float4*)(sm + OFF_IN);
        float a0 = rb1, a1 = rb1, b0 = 0.f, b1 = 0.f;
#pragma unroll
        for (int c = 0; c < 12; c++) {
            float2 wr[4]; float4 xr[4];
#pragma unroll
            for (int i = 0; i < 4; i++) { wr[i] = wp[(c * 4 + i) * 275]; xr[i] = x4[c * 4 + i]; }
#pragma unroll
            for (int i = 0; i < 4; i++) {
                a0 = fmaf(wr[i].x, xr[i].x, a0); a1 = fmaf(wr[i].x, xr[i].y, a1);
                b0 = fmaf(wr[i].y, xr[i].z, b0); b1 = fmaf(wr[i].y, xr[i].w, b1);
            }
        }
#pragma unroll
        for (int kp = 48; kp < 51; kp++) {
            float2 w = wp[kp * 275]; float4 x = x4[kp];
            a0 = fmaf(w.x, x.x, a0); a1 = fmaf(w.x, x.y, a1);
            b0 = fmaf(w.y, x.z, b0); b1 = fmaf(w.y, x.w, b1);
        }
        s_hid[tid] = make_float2(ftanh(a0 + b0), ftanh(a1 + b1));
    }
    __syncthreads();

    // ---- L2: 275 -> 275, ring-buffered stream, k-split over 2 groups ----
    float4 acc;
    if (act) {
        const float2* x2 = ((const float2*)(sm + OFF_HID)) + g * 138;
        float4 ac = make_float4(0.f, 0.f, 0.f, 0.f);
        float4 bc = make_float4(0.f, 0.f, 0.f, 0.f);
        W2_CONSUME(r0, 0) W2_REFILL(r0, 48)
        W2_CONSUME(r1, 1) W2_REFILL(r1, 64)
        W2_CONSUME(r2, 2) W2_REFILL(r2, 80)
        W2_CONSUME(r0, 3) W2_REFILL(r0, 96)
        W2_CONSUME(r1, 4) W2_REFILL(r1, 112)
        W2_CONSUME(r2, 5)
        W2_CONSUME(r0, 6)
        W2_CONSUME(r1, 7)
#pragma unroll
        for (int i = 0; i < 10; i++) {
            float2 xv = x2[128 + i];
            if (i & 1) {
                bc.x = fmaf(tl[i].x, xv.x, bc.x); bc.y = fmaf(tl[i].x, xv.y, bc.y);
                bc.z = fmaf(tl[i].y, xv.x, bc.z); bc.w = fmaf(tl[i].y, xv.y, bc.w);
            } else {
                ac.x = fmaf(tl[i].x, xv.x, ac.x); ac.y = fmaf(tl[i].x, xv.y, ac.y);
                ac.z = fmaf(tl[i].y, xv.x, ac.z); ac.w = fmaf(tl[i].y, xv.y, ac.w);
            }
        }
        acc = make_float4(ac.x + bc.x, ac.y + bc.y, ac.z + bc.z, ac.w + bc.w);
        if (g) s_p4[j] = acc;
    }
    __syncthreads();
    if (act && !g) {
        float4 pp = s_p4[j];
        s_a2[n0]     = make_float2(ftanh(acc.x + pp.x + rb2a), ftanh(acc.y + pp.y + rb2a));
        s_a2[n0 + 1] = make_float2(ftanh(acc.z + pp.z + rb2b), ftanh(acc.w + pp.w + rb2b));
    }
    __syncthreads();

    // ---- L3: 275 -> 100 (W3P paired in smem, k-split), fused RK4 update ----
    float2 a3 = make_float2(0.f, 0.f);
    if (tid < 100) {
        a3 = dotW3(((const float2*)(sm + OFF_W3P)) + tid, (const float2*)(sm + OFF_A2));
    } else if (tid < 200) {
        s_p2[tid - 100] = dotW3(((const float2*)(sm + OFF_W3P)) + 69 * 100 + (tid - 100),
                                ((const float2*)(sm + OFF_A2)) + 138);
    }
    __syncthreads();
    if (tid < 100) {
        float2 pp = s_p2[tid];
        float2 f = make_float2(ftanh(a3.x + pp.x + rb3), ftanh(a3.y + pp.y + rb3));
        if (stage == 0) {
            rks = f;
            s_in[1 + tid] = make_float2(fmaf(0.5f * dt.x, f.x, ry.x),
                                        fmaf(0.5f * dt.y, f.y, ry.y));
        } else if (stage == 1) {
            rks = make_float2(rks.x + 2.f * f.x, rks.y + 2.f * f.y);
            s_in[1 + tid] = make_float2(fmaf(0.5f * dt.x, f.x, ry.x),
                                        fmaf(0.5f * dt.y, f.y, ry.y));
        } else if (stage == 2) {
            rks = make_float2(rks.x + 2.f * f.x, rks.y + 2.f * f.y);
            s_in[1 + tid] = make_float2(fmaf(dt.x, f.x, ry.x),
                                        fmaf(dt.y, f.y, ry.y));
        } else {
            ry = make_float2(ry.x + dt.x * (rks.x + f.x) / 6.f,
                             ry.y + dt.y * (rks.y + f.y) / 6.f);
            if (write_in) s_in[1 + tid] = ry;
            if (write_y)  s_y[tid] = ry;
        }
        if (tid == 0 && (stage < 3 || write_in)) s_in[0] = tnext;
    }
    __syncthreads();
}

// ---- RK4, NSUB=2. ry (tid<100) carries y; s_y refreshed at the end. ----
__device__ __forceinline__ void integrate2(int tid, float* sm, float2 t0, float2 t1,
        float2& ry, float rb1, float rb2a, float rb2b, float rb3) {
    float2* s_in = (float2*)(sm + OFF_IN);
    float2 dt = make_float2((t1.x - t0.x) * 0.5f, (t1.y - t0.y) * 0.5f);
    if (tid < HH) s_in[1 + tid] = ry;
    if (tid == 0) s_in[0] = t0;
    __syncthreads();
    float2 rks = make_float2(0.f, 0.f);
#pragma unroll 1
    for (int st = 0; st < 8; st++) {
        int stage = st & 3, sub = st >> 2;
        float2 tb = make_float2(t0.x + sub * dt.x, t0.y + sub * dt.y);
        float2 tnext = (stage <= 1)
            ? make_float2(tb.x + 0.5f * dt.x, tb.y + 0.5f * dt.y)
            : make_float2(tb.x + dt.x, tb.y + dt.y);
        field_stage(tid, sm, stage, dt, tnext, (st == 3), (st == 7),
                    ry, rks, rb1, rb2a, rb2b, rb3);
    }
}

// ---- prep: build packed/transposed weight copies ----
__global__ void prep_kernel(const float* __restrict__ fW1, const float* __restrict__ fW2,
                            const float* __restrict__ fW3, const float* __restrict__ Whh,
                            const float* __restrict__ oW1, const float* __restrict__ oW2) {
    for (int i = blockIdx.x * blockDim.x + threadIdx.x; i < 174953;
         i += gridDim.x * blockDim.x) {
        if (i < 55652) {
            if (i < 28050) {
                int q = i >> 1, r = i & 1;
                int kp = q / 275, n = q % 275;
                int k = 2 * kp + r;
                g_W13P[i] = (k < 101) ? fW1[n * 101 + k] : 0.f;
            } else if (i < 28052) {
                g_W13P[i] = 0.f;
            } else {
                int jj = i - 28052;
                int q = jj >> 1, r = jj & 1;
                int hk = q / 100, n = q % 100;
                int half = hk / 69, kp = hk % 69;
                int k = half * 138 + 2 * kp + r;
                g_W13P[i] = (k < 275) ? fW3[n * 275 + k] : 0.f;
            }
        } else if (i < 131828) {
            int jj = i - 55652, k = jj / 276, n = jj % 276;
            g_W2T[jj] = (n < 275 && k < 275) ? fW2[n * 275 + k] : 0.f;
        } else if (i < 161828) {
            int jj = i - 131828, k = jj / 300, n = jj % 300;
            g_WhhT[jj] = Whh[n * 100 + k];
        } else if (i < 169328) {
            int jj = i - 161828, k = jj / 75, n = jj % 75;
            g_oW1T[jj] = oW1[n * 100 + k];
        } else {
            int jj = i - 169328, k = jj / 75, n = jj % 75;
            g_oW2T[jj] = oW2[n * 75 + k];
        }
    }
}

// ---- encode ----
__global__ void __launch_bounds__(NTHR, 1) encode_kernel(
        const float* __restrict__ past, const float* __restrict__ h0,
        const float* __restrict__ fb1, const float* __restrict__ fb2,
        const float* __restrict__ fb3,
        const float* __restrict__ Wih, const float* __restrict__ bih,
        const float* __restrict__ bhh) {
    extern __shared__ float sm[];
    int tid = threadIdx.x;
    int r0 = blockIdx.x * 2, r1 = r0 + 1;

    const float4* src = (const float4*)g_W13P;
    float4* dst = (float4*)sm;
    for (int i = tid; i < 55652 / 4; i += NTHR) dst[i] = src[i];

    float rb1 = (tid < NF) ? __ldg(fb1 + tid) : 0.f;
    int g = tid / 144, j = tid - g * 144;
    float rb2a = 0.f, rb2b = 0.f;
    if (g == 0 && j < 138) {
        rb2a = __ldg(fb2 + 2 * j);
        rb2b = (2 * j + 1 < NF) ? __ldg(fb2 + 2 * j + 1) : 0.f;
    }
    float rb3 = (tid < HH) ? __ldg(fb3 + tid) : 0.f;

    float2* s_u   = (float2*)(sm + OFF_HID);   // [200] aliased
    float2* s_inn = (float2*)(sm + OFF_A2);    // [100]
    float2* s_hn  = (float2*)(sm + OFF_PART);  // [100]
    float2 ry = make_float2(0.f, 0.f);
    if (tid < HH) ry = make_float2(h0[r0 * HH + tid], h0[r1 * HH + tid]);
    if (tid == 0) {
        ((float2*)(sm + OFF_HID))[275] = make_float2(0.f, 0.f);
        ((float2*)(sm + OFF_IN))[101] = make_float2(0.f, 0.f);
    }
    __syncthreads();

    float2 tprev = make_float2(0.f, 0.f);
    for (int step = 0; step < TP; step++) {
        float2 tcur = make_float2(past[(r0 * TP + step) * 2], past[(r1 * TP + step) * 2]);
        float2 t0 = (step == 0) ? make_float2(tcur.x - 1.f, tcur.y - 1.f) : tprev;
        integrate2(tid, sm, t0, tcur, ry, rb1, rb2a, rb2b, rb3);
        // s_y now holds the integrated state for all threads to read.

        float2 x = make_float2(past[(r0 * TP + step) * 2 + 1],
                               past[(r1 * TP + step) * 2 + 1]);
        const float4* y4 = (const float4*)(sm + OFF_Y);
        for (int jj = tid; jj < 300; jj += NTHR) {
            float bh = __ldg(bhh + jj);
            float a0 = bh, a1 = bh, b0 = 0.f, b1 = 0.f;
#pragma unroll 10
            for (int k = 0; k < 100; k += 2) {
                float w0 = __ldcg(g_WhhT + k * 300 + jj);
                float w1 = __ldcg(g_WhhT + (k + 1) * 300 + jj);
                float4 y = y4[k >> 1];
                a0 = fmaf(w0, y.x, a0); a1 = fmaf(w0, y.y, a1);
                b0 = fmaf(w1, y.z, b0); b1 = fmaf(w1, y.w, b1);
            }
            a0 += b0; a1 += b1;
            float wi = __ldg(Wih + jj), bi = __ldg(bih + jj);
            float2 gi = make_float2(fmaf(wi, x.x, bi), fmaf(wi, x.y, bi));
            if (jj < 200) s_u[jj] = make_float2(gi.x + a0, gi.y + a1);
            else { s_inn[jj - 200] = gi; s_hn[jj - 200] = make_float2(a0, a1); }
        }
        __syncthreads();
        if (tid < HH) {
            float2 u1 = s_u[tid], u2 = s_u[HH + tid];
            float2 gin = s_inn[tid], ghn = s_hn[tid];
            float rx = fsigm(u1.x), ryy = fsigm(u1.y);
            float zx = fsigm(u2.x), zy = fsigm(u2.y);
            float nx = ftanh(gin.x + rx * ghn.x), ny = ftanh(gin.y + ryy * ghn.y);
            ry = make_float2((1.f - zx) * nx + zx * ry.x,
                             (1.f - zy) * ny + zy * ry.y);
        }
        __syncthreads();   // s_u/s_inn/s_hn reads done before next stage reuses buffers
        tprev = tcur;
    }
    if (tid < HH) {
        g_hB[r0 * HH + tid] = ry.x;
        g_hB[r1 * HH + tid] = ry.y;
    }
}

// ---- decoder head ----
__global__ void gx_kernel(const float* __restrict__ gW1, const float* __restrict__ gb1,
                          const float* __restrict__ gW2, const float* __restrict__ gb2,
                          const float* __restrict__ gW3, const float* __restrict__ gb3) {
    int b = blockIdx.x, tid = threadIdx.x;
    __shared__ float sh[HH], s1[HGG], s2[HGG];
    for (int k = tid; k < HH; k += blockDim.x) sh[k] = g_hB[b * HH + k];
    __syncthreads();
    if (tid < HGG) {
        float a = __ldg(gb1 + tid);
        const float* w = gW1 + tid * HH;
        for (int k = 0; k < HH; k++) a = fmaf(__ldg(w + k), sh[k], a);
        s1[tid] = leaky1(a);
    }
    __syncthreads();
    if (tid < HGG) {
        float a = __ldg(gb2 + tid);
        const float* w = gW2 + tid * HGG;
        for (int k = 0; k < HGG; k++) a = fmaf(__ldg(w + k), s1[k], a);
        s2[tid] = leaky1(a);
    }
    __syncthreads();
    if (tid < 2) {
        float a = __ldg(gb3 + tid);
        const float* w = gW3 + tid * HGG;
        for (int k = 0; k < HGG; k++) a = fmaf(__ldg(w + k), s2[k], a);
        g_gx[b * 2 + tid] = a;
    }
}

__global__ void z0_kernel(const float* __restrict__ eps) {
    int b = blockIdx.x, h = threadIdx.x;
    float loc, scale;
    if (b < NB / 2) {
        loc   = g_gx[(2 * b) * 2 + 0];
        scale = g_gx[(2 * b + 1) * 2 + 0];
    } else {
        int i = 2 * (b - NB / 2);
        loc   = fabsf(g_gx[i * 2 + 1]);
        scale = fabsf(g_gx[(i + 1) * 2 + 1]);
    }
    g_z0[b * HH + h] = loc + scale * eps[h * NB + b];
}

// ---- rollout output MLP ----
__device__ __forceinline__ void out_mlp(int tid, int s, int r0, int r1, float* sm,
        float rob1, float rob2,
        const float* __restrict__ oW3, const float* __restrict__ ob3,
        float* __restrict__ out) {
    float2* s_o1 = (float2*)(sm + OFF_HID);
    float2* s_o2 = (float2*)(sm + OFF_A2);
    if (tid < HOO) {
        const float4* y4 = (const float4*)(sm + OFF_Y);
        float a0 = rob1, a1 = rob1, b0 = 0.f, b1 = 0.f;
#pragma unroll 10
        for (int k = 0; k < 100; k += 2) {
            float w0 = __ldcg(g_oW1T + k * 75 + tid);
            float w1 = __ldcg(g_oW1T + (k + 1) * 75 + tid);
            float4 y = y4[k >> 1];
            a0 = fmaf(w0, y.x, a0); a1 = fmaf(w0, y.y, a1);
            b0 = fmaf(w1, y.z, b0); b1 = fmaf(w1, y.w, b1);
        }
        s_o1[tid] = make_float2(leaky1(a0 + b0), leaky1(a1 + b1));
    }
    __syncthreads();
    if (tid < HOO) {
        const float4* h4 = (const float4*)(sm + OFF_HID);
        float a0 = rob2, a1 = rob2, b0 = 0.f, b1 = 0.f;
#pragma unroll 8
        for (int k = 0; k + 1 < HOO; k += 2) {
            float w0 = __ldcg(g_oW2T + k * 75 + tid);
            float w1 = __ldcg(g_oW2T + (k + 1) * 75 + tid);
            float4 h = h4[k >> 1];
            a0 = fmaf(w0, h.x, a0); a1 = fmaf(w0, h.y, a1);
            b0 = fmaf(w1, h.z, b0); b1 = fmaf(w1, h.w, b1);
        }
        {
            float w0 = __ldcg(g_oW2T + 74 * 75 + tid);
            float2 h = s_o1[74];
            a0 = fmaf(w0, h.x, a0); a1 = fmaf(w0, h.y, a1);
        }
        s_o2[tid] = make_float2(leaky1(a0 + b0), leaky1(a1 + b1));
    }
    __syncthreads();
    if (tid < 32) {
        float a0 = 0.f, a1 = 0.f;
        for (int k = tid; k < HOO; k += 32) {
            float wv = __ldg(oW3 + k);
            float2 h = s_o2[k];
            a0 = fmaf(wv, h.x, a0); a1 = fmaf(wv, h.y, a1);
        }
#pragma unroll
        for (int o = 16; o; o >>= 1) {
            a0 += __shfl_down_sync(0xffffffffu, a0, o);
            a1 += __shfl_down_sync(0xffffffffu, a1, o);
        }
        if (tid == 0) {
            float b = __ldg(ob3);
            out[r0 * TFUT + s] = a0 + b;
            out[r1 * TFUT + s] = a1 + b;
        }
    }
    __syncthreads();
}

__global__ void __launch_bounds__(NTHR, 1) rollout_kernel(
        const float* __restrict__ tf_,
        const float* __restrict__ fb1, const float* __restrict__ fb2,
        const float* __restrict__ fb3,
        const float* __restrict__ ob1, const float* __restrict__ ob2,
        const float* __restrict__ oW3, const float* __restrict__ ob3,
        float* __restrict__ out) {
    extern __shared__ float sm[];
    int tid = threadIdx.x;
    int r0 = blockIdx.x * 2, r1 = r0 + 1;

    const float4* src = (const float4*)g_W13P;
    float4* dst = (float4*)sm;
    for (int i = tid; i < 55652 / 4; i += NTHR) dst[i] = src[i];

    float rb1 = (tid < NF) ? __ldg(fb1 + tid) : 0.f;
    int g = tid / 144, j = tid - g * 144;
    float rb2a = 0.f, rb2b = 0.f;
    if (g == 0 && j < 138) {
        rb2a = __ldg(fb2 + 2 * j);
        rb2b = (2 * j + 1 < NF) ? __ldg(fb2 + 2 * j + 1) : 0.f;
    }
    float rb3 = (tid < HH) ? __ldg(fb3 + tid) : 0.f;
    float rob1 = (tid < HOO) ? __ldg(ob1 + tid) : 0.f;
    float rob2 = (tid < HOO) ? __ldg(ob2 + tid) : 0.f;

    float2* s_y = (float2*)(sm + OFF_Y);
    float2 ry = make_float2(0.f, 0.f);
    if (tid < HH) {
        ry = make_float2(g_z0[r0 * HH + tid], g_z0[r1 * HH + tid]);
        s_y[tid] = ry;
    }
    if (tid == 0) {
        ((float2*)(sm + OFF_HID))[275] = make_float2(0.f, 0.f);
        ((float2*)(sm + OFF_IN))[101] = make_float2(0.f, 0.f);
    }
    __syncthreads();

    out_mlp(tid, 0, r0, r1, sm, rob1, rob2, oW3, ob3, out);

    float2 tprev = make_float2(tf_[r0 * TFUT], tf_[r1 * TFUT]);
    for (int s = 1; s < TFUT; s++) {
        float2 tcur = make_float2(tf_[r0 * TFUT + s], tf_[r1 * TFUT + s]);
        integrate2(tid, sm, tprev, tcur, ry, rb1, rb2a, rb2b, rb3);
        out_mlp(tid, s, r0, r1, sm, rob1, rob2, oW3, ob3, out);
        tprev = tcur;
    }
}

extern "C" void kernel_launch(void* const* d_in, const int* in_sizes, int n_in,
                              void* d_out, int out_size) {
    const float* past = (const float*)d_in[0];
    const float* h0   = (const float*)d_in[1];
    const float* t_fu = (const float*)d_in[2];
    const float* eps  = (const float*)d_in[3];
    const float* fW1  = (const float*)d_in[4];
    const float* fb1  = (const float*)d_in[5];
    const float* fW2  = (const float*)d_in[6];
    const float* fb2  = (const float*)d_in[7];
    const float* fW3  = (const float*)d_in[8];
    const float* fb3  = (const float*)d_in[9];
    const float* Wih  = (const float*)d_in[10];
    const float* Whh  = (const float*)d_in[11];
    const float* bih  = (const float*)d_in[12];
    const float* bhh  = (const float*)d_in[13];
    const float* gW1  = (const float*)d_in[14];
    const float* gb1  = (const float*)d_in[15];
    const float* gW2  = (const float*)d_in[16];
    const float* gb2  = (const float*)d_in[17];
    const float* gW3  = (const float*)d_in[18];
    const float* gb3  = (const float*)d_in[19];
    const float* oW1  = (const float*)d_in[20];
    const float* ob1  = (const float*)d_in[21];
    const float* oW2  = (const float*)d_in[22];
    const float* ob2  = (const float*)d_in[23];
    const float* oW3  = (const float*)d_in[24];
    const float* ob3  = (const float*)d_in[25];
    float* out = (float*)d_out;

    static bool attr_done = false;
    if (!attr_done) {
        cudaFuncSetAttribute(encode_kernel,
                             cudaFuncAttributeMaxDynamicSharedMemorySize, SMEM_BYTES);
        cudaFuncSetAttribute(rollout_kernel,
                             cudaFuncAttributeMaxDynamicSharedMemorySize, SMEM_BYTES);
        attr_done = true;
    }

    prep_kernel<<<192, 256>>>(fW1, fW2, fW3, Whh, oW1, oW2);
    encode_kernel<<<NCTA, NTHR, SMEM_BYTES>>>(past, h0, fb1, fb2, fb3, Wih, bih, bhh);
    gx_kernel<<<NB, 96>>>(gW1, gb1, gW2, gb2, gW3, gb3);
    z0_kernel<<<NB, HH>>>(eps);
    rollout_kernel<<<NCTA, NTHR, SMEM_BYTES>>>(t_fu, fb1, fb2, fb3,
                                               ob1, ob2, oW3, ob3, out);
}

// round 12
// speedup vs baseline: 1.5747x; 1.1384x over previous
#include <cuda_runtime.h>
#include <cuda_fp16.h>
#include <math.h>

#define NB    256
#define TP    32
#define TFUT  256
#define HH    100
#define NF    275
#define HGG   75
#define HOO   75
#define NTHR  288
#define NCTA  128

typedef unsigned long long ull;

// ---- transposed/packed weights in global scratch ----
// g_W13P: [0,28050) W1P[(kp*275+n)*2+r] (k=2kp+r); [28050,28052) pad;
//         [28052,55652) W3P[((half*69+kp)*100+n)*2+r] (k=half*138+2kp+r, k=275 -> 0)
__device__ __align__(16) float g_W13P[55652];
// W2 in fp16: g_W2H[k*138 + j] = half2(fW2[(2j)*275+k], fW2[(2j+1)*275+k]); row 275 = 0, col 275 = 0
__device__ __align__(16) __half2 g_W2H[276 * 138];
__device__ __align__(16) float g_WhhT[100 * 300];
__device__ __align__(16) float g_oW1T[100 * 75];
__device__ __align__(16) float g_oW2T[75 * 75];
__device__ float g_hB[NB * HH];
__device__ float g_gx[NB * 2];
__device__ float g_z0[NB * HH];

// ---- shared layout (float offsets), total 57912 floats = 231,648 B ----
#define OFF_W1P  0
#define OFF_W3P  28052
#define OFF_IN   55652   // float2[102] (slot 101 = zero pad)
#define OFF_HID  55856   // float2[276] (slot 275 = zero pad)
#define OFF_A2   56408   // float2[276]
#define OFF_Y    56960   // float2[100]
#define OFF_KS   57160   // float2[100]
#define OFF_PART 57360   // float4[138]
#define SMEM_BYTES (57912 * 4)

__device__ __forceinline__ float leaky1(float x) {
    const float SL = 1.0f / 5.5f;
    return x >= 0.f ? x : x * SL;
}
__device__ __forceinline__ float sigm1(float x) { return 1.f / (1.f + expf(-x)); }

// ---- packed fp32x2 FMA (Blackwell FFMA2) ----
#define FMA_X2(ACC, W, X) \
    asm("fma.rn.f32x2 %0, %1, %2, %0;" : "+l"(ACC) : "l"(W), "l"(X))

// ---- W2 fp16 ring-pipeline macros (16-row chunks, 2 output cols per thread) ----
#define W2H_REFILL(R, ROW0)                                                   \
    _Pragma("unroll")                                                         \
    for (int i_ = 0; i_ < 16; i_++)                                           \
        R[i_] = __ldcg((const unsigned int*)(ph + ((ROW0) + i_) * 138));

// Consume one 16-row chunk. Accumulators: acA=(n0:r0,r1), acB=(n1:r0,r1) + 2nd chains.
#define W2H_CONSUME(R, C) {                                                   \
    const ull* xu_ = (const ull*)(x2 + (C) * 16);                             \
    _Pragma("unroll")                                                         \
    for (int ii_ = 0; ii_ < 16; ii_++) {                                      \
        float2 wf_ = __half22float2(*(const __half2*)&R[ii_]);                \
        ull wa_, wb_, xv_ = xu_[ii_];                                         \
        asm("mov.b64 %0, {%1, %1};" : "=l"(wa_) : "f"(wf_.x));                \
        asm("mov.b64 %0, {%1, %1};" : "=l"(wb_) : "f"(wf_.y));                \
        if (ii_ & 1) { FMA_X2(acA2, wa_, xv_); FMA_X2(acB2, wb_, xv_); }      \
        else         { FMA_X2(acA,  wa_, xv_); FMA_X2(acB,  wb_, xv_); }      \
    } }

// ---- Layer-3 partial: output n, one k-half (69 pairs), W3P in SMEM ----
__device__ __forceinline__ float2 dotW3(const float2* __restrict__ wp,
                                        const float2* __restrict__ x2base) {
    const float4* x4 = (const float4*)x2base;
    float a0 = 0.f, a1 = 0.f, b0 = 0.f, b1 = 0.f;
#pragma unroll
    for (int c = 0; c < 17; c++) {
        float2 wr[4]; float4 xr[4];
#pragma unroll
        for (int i = 0; i < 4; i++) { wr[i] = wp[(c * 4 + i) * 100]; xr[i] = x4[c * 4 + i]; }
#pragma unroll
        for (int i = 0; i < 4; i++) {
            a0 = fmaf(wr[i].x, xr[i].x, a0); a1 = fmaf(wr[i].x, xr[i].y, a1);
            b0 = fmaf(wr[i].y, xr[i].z, b0); b1 = fmaf(wr[i].y, xr[i].w, b1);
        }
    }
    {   // kp = 68
        float2 w = wp[68 * 100]; float4 x = x4[68];
        a0 = fmaf(w.x, x.x, a0); a1 = fmaf(w.x, x.y, a1);
        b0 = fmaf(w.y, x.z, b0); b1 = fmaf(w.y, x.w, b1);
    }
    return make_float2(a0 + b0, a1 + b1);
}

// ---- One RK4 stage: W2 prefetch -> L1 -> L2(pipelined) -> L3 -> fused update ----
__device__ __forceinline__ void field_stage(int tid, float* sm, int stage,
        float2 dt, float2 tnext, bool write_in,
        float rb1, float rb2a, float rb2b, float rb3) {
    float2* s_in  = (float2*)(sm + OFF_IN);
    float2* s_hid = (float2*)(sm + OFF_HID);
    float2* s_a2  = (float2*)(sm + OFF_A2);
    float2* s_y   = (float2*)(sm + OFF_Y);
    float2* s_ks  = (float2*)(sm + OFF_KS);
    float4* s_p4  = (float4*)(sm + OFF_PART);
    float2* s_p2  = (float2*)(sm + OFF_PART);

    int g = tid / 144, j = tid - g * 144;
    bool act = (j < 138);
    int n0 = 2 * j;
    const __half2* ph = g_W2H + (g * 138) * 138 + j;

    // ---- W2 prefetch: rows 0..47 + tail 128..137 issued BEFORE L1 compute ----
    unsigned int r0[16], r1[16], r2[16], tl[10];
    if (act) {
        W2H_REFILL(r0, 0)
        W2H_REFILL(r1, 16)
        W2H_REFILL(r2, 32)
#pragma unroll
        for (int i = 0; i < 10; i++)
            tl[i] = __ldcg((const unsigned int*)(ph + (128 + i) * 138));
    }

    // ---- L1: 101 -> 275 (W1P paired in smem) ----
    if (tid < NF) {
        const float2* wp = ((const float2*)(sm + OFF_W1P)) + tid;
        const float4* x4 = (const float4*)(sm + OFF_IN);
        float a0 = rb1, a1 = rb1, b0 = 0.f, b1 = 0.f;
#pragma unroll
        for (int c = 0; c < 12; c++) {
            float2 wr[4]; float4 xr[4];
#pragma unroll
            for (int i = 0; i < 4; i++) { wr[i] = wp[(c * 4 + i) * 275]; xr[i] = x4[c * 4 + i]; }
#pragma unroll
            for (int i = 0; i < 4; i++) {
                a0 = fmaf(wr[i].x, xr[i].x, a0); a1 = fmaf(wr[i].x, xr[i].y, a1);
                b0 = fmaf(wr[i].y, xr[i].z, b0); b1 = fmaf(wr[i].y, xr[i].w, b1);
            }
        }
#pragma unroll
        for (int kp = 48; kp < 51; kp++) {
            float2 w = wp[kp * 275]; float4 x = x4[kp];
            a0 = fmaf(w.x, x.x, a0); a1 = fmaf(w.x, x.y, a1);
            b0 = fmaf(w.y, x.z, b0); b1 = fmaf(w.y, x.w, b1);
        }
        s_hid[tid] = make_float2(tanhf(a0 + b0), tanhf(a1 + b1));
    }
    __syncthreads();

    // ---- L2: 275 -> 275, fp16 weights, packed f32x2 FMA, ring-buffered stream ----
    float4 acc;
    if (act) {
        const float2* x2 = ((const float2*)(sm + OFF_HID)) + g * 138;
        ull acA = 0ull, acA2 = 0ull, acB = 0ull, acB2 = 0ull;
        W2H_CONSUME(r0, 0) W2H_REFILL(r0, 48)
        W2H_CONSUME(r1, 1) W2H_REFILL(r1, 64)
        W2H_CONSUME(r2, 2) W2H_REFILL(r2, 80)
        W2H_CONSUME(r0, 3) W2H_REFILL(r0, 96)
        W2H_CONSUME(r1, 4) W2H_REFILL(r1, 112)
        W2H_CONSUME(r2, 5)
        W2H_CONSUME(r0, 6)
        W2H_CONSUME(r1, 7)
#pragma unroll
        for (int i = 0; i < 10; i++) {       // tail rows k = 128..137
            float2 wf = __half22float2(*(const __half2*)&tl[i]);
            ull wa, wb, xv = ((const ull*)x2)[128 + i];
            asm("mov.b64 %0, {%1, %1};" : "=l"(wa) : "f"(wf.x));
            asm("mov.b64 %0, {%1, %1};" : "=l"(wb) : "f"(wf.y));
            if (i & 1) { FMA_X2(acA2, wa, xv); FMA_X2(acB2, wb, xv); }
            else       { FMA_X2(acA,  wa, xv); FMA_X2(acB,  wb, xv); }
        }
        ull sA, sB;
        asm("add.rn.f32x2 %0, %1, %2;" : "=l"(sA) : "l"(acA), "l"(acA2));
        asm("add.rn.f32x2 %0, %1, %2;" : "=l"(sB) : "l"(acB), "l"(acB2));
        float2 fA = *(float2*)&sA, fB = *(float2*)&sB;
        acc = make_float4(fA.x, fA.y, fB.x, fB.y);
        if (g) s_p4[j] = acc;
    }
    __syncthreads();
    if (act && !g) {
        float4 pp = s_p4[j];
        s_a2[n0]     = make_float2(tanhf(acc.x + pp.x + rb2a), tanhf(acc.y + pp.y + rb2a));
        s_a2[n0 + 1] = make_float2(tanhf(acc.z + pp.z + rb2b), tanhf(acc.w + pp.w + rb2b));
    }
    __syncthreads();

    // ---- L3: 275 -> 100 (W3P paired in smem, k-split), fused RK4 update ----
    float2 a3 = make_float2(0.f, 0.f);
    if (tid < 100) {
        a3 = dotW3(((const float2*)(sm + OFF_W3P)) + tid, (const float2*)(sm + OFF_A2));
    } else if (tid < 200) {
        s_p2[tid - 100] = dotW3(((const float2*)(sm + OFF_W3P)) + 69 * 100 + (tid - 100),
                                ((const float2*)(sm + OFF_A2)) + 138);
    }
    __syncthreads();
    if (tid < 100) {
        float2 pp = s_p2[tid];
        float2 f = make_float2(tanhf(a3.x + pp.x + rb3), tanhf(a3.y + pp.y + rb3));
        float2 y = s_y[tid];
        if (stage == 0) {
            s_ks[tid] = f;
            s_in[1 + tid] = make_float2(fmaf(0.5f * dt.x, f.x, y.x),
                                        fmaf(0.5f * dt.y, f.y, y.y));
        } else if (stage == 1) {
            float2 k = s_ks[tid];
            s_ks[tid] = make_float2(k.x + 2.f * f.x, k.y + 2.f * f.y);
            s_in[1 + tid] = make_float2(fmaf(0.5f * dt.x, f.x, y.x),
                                        fmaf(0.5f * dt.y, f.y, y.y));
        } else if (stage == 2) {
            float2 k = s_ks[tid];
            s_ks[tid] = make_float2(k.x + 2.f * f.x, k.y + 2.f * f.y);
            s_in[1 + tid] = make_float2(fmaf(dt.x, f.x, y.x),
                                        fmaf(dt.y, f.y, y.y));
        } else {
            float2 k = s_ks[tid];
            float2 yn = make_float2(y.x + dt.x * (k.x + f.x) / 6.f,
                                    y.y + dt.y * (k.y + f.y) / 6.f);
            s_y[tid] = yn;
            if (write_in) s_in[1 + tid] = yn;
        }
        if (tid == 0 && (stage < 3 || write_in)) s_in[0] = tnext;
    }
    __syncthreads();
}

// ---- RK4, NSUB=2 ----
__device__ __forceinline__ void integrate2(int tid, float* sm, float2 t0, float2 t1,
        float rb1, float rb2a, float rb2b, float rb3) {
    float2* s_in = (float2*)(sm + OFF_IN);
    float2* s_y  = (float2*)(sm + OFF_Y);
    float2 dt = make_float2((t1.x - t0.x) * 0.5f, (t1.y - t0.y) * 0.5f);
    if (tid < HH) s_in[1 + tid] = s_y[tid];
    if (tid == 0) s_in[0] = t0;
    __syncthreads();
#pragma unroll 1
    for (int st = 0; st < 8; st++) {
        int stage = st & 3, sub = st >> 2;
        float2 tb = make_float2(t0.x + sub * dt.x, t0.y + sub * dt.y);
        float2 tnext = (stage <= 1)
            ? make_float2(tb.x + 0.5f * dt.x, tb.y + 0.5f * dt.y)
            : make_float2(tb.x + dt.x, tb.y + dt.y);
        field_stage(tid, sm, stage, dt, tnext, (st == 3), rb1, rb2a, rb2b, rb3);
    }
}

// ---- prep: build packed/transposed weight copies ----
__global__ void prep_kernel(const float* __restrict__ fW1, const float* __restrict__ fW2,
                            const float* __restrict__ fW3, const float* __restrict__ Whh,
                            const float* __restrict__ oW1, const float* __restrict__ oW2) {
    for (int i = blockIdx.x * blockDim.x + threadIdx.x; i < 136865;
         i += gridDim.x * blockDim.x) {
        if (i < 55652) {
            if (i < 28050) {
                int q = i >> 1, r = i & 1;
                int kp = q / 275, n = q % 275;
                int k = 2 * kp + r;
                g_W13P[i] = (k < 101) ? fW1[n * 101 + k] : 0.f;
            } else if (i < 28052) {
                g_W13P[i] = 0.f;
            } else {
                int jj = i - 28052;
                int q = jj >> 1, r = jj & 1;
                int hk = q / 100, n = q % 100;
                int half = hk / 69, kp = hk % 69;
                int k = half * 138 + 2 * kp + r;
                g_W13P[i] = (k < 275) ? fW3[n * 275 + k] : 0.f;
            }
        } else if (i < 93740) {
            int idx = i - 55652;
            int k = idx / 138, jj = idx % 138;
            int n0 = 2 * jj, n1 = 2 * jj + 1;
            float v0 = (k < 275) ? fW2[n0 * 275 + k] : 0.f;
            float v1 = (k < 275 && n1 < 275) ? fW2[n1 * 275 + k] : 0.f;
            g_W2H[idx] = __floats2half2_rn(v0, v1);
        } else if (i < 123740) {
            int jj = i - 93740, k = jj / 300, n = jj % 300;
            g_WhhT[jj] = Whh[n * 100 + k];
        } else if (i < 131240) {
            int jj = i - 123740, k = jj / 75, n = jj % 75;
            g_oW1T[jj] = oW1[n * 100 + k];
        } else {
            int jj = i - 131240, k = jj / 75, n = jj % 75;
            g_oW2T[jj] = oW2[n * 75 + k];
        }
    }
}

// ---- encode ----
__global__ void __launch_bounds__(NTHR, 1) encode_kernel(
        const float* __restrict__ past, const float* __restrict__ h0,
        const float* __restrict__ fb1, const float* __restrict__ fb2,
        const float* __restrict__ fb3,
        const float* __restrict__ Wih, const float* __restrict__ bih,
        const float* __restrict__ bhh) {
    extern __shared__ float sm[];
    int tid = threadIdx.x;
    int r0 = blockIdx.x * 2, r1 = r0 + 1;

    const float4* src = (const float4*)g_W13P;
    float4* dst = (float4*)sm;
    for (int i = tid; i < 55652 / 4; i += NTHR) dst[i] = src[i];

    float rb1 = (tid < NF) ? __ldg(fb1 + tid) : 0.f;
    int g = tid / 144, j = tid - g * 144;
    float rb2a = 0.f, rb2b = 0.f;
    if (g == 0 && j < 138) {
        rb2a = __ldg(fb2 + 2 * j);
        rb2b = (2 * j + 1 < NF) ? __ldg(fb2 + 2 * j + 1) : 0.f;
    }
    float rb3 = (tid < HH) ? __ldg(fb3 + tid) : 0.f;

    float2* s_y   = (float2*)(sm + OFF_Y);
    float2* s_u   = (float2*)(sm + OFF_HID);   // [200] aliased
    float2* s_inn = (float2*)(sm + OFF_A2);    // [100]
    float2* s_hn  = (float2*)(sm + OFF_PART);  // [100]
    if (tid < HH) s_y[tid] = make_float2(h0[r0 * HH + tid], h0[r1 * HH + tid]);
    if (tid == 0) {
        ((float2*)(sm + OFF_HID))[275] = make_float2(0.f, 0.f);
        ((float2*)(sm + OFF_IN))[101] = make_float2(0.f, 0.f);
    }
    __syncthreads();

    float2 tprev = make_float2(0.f, 0.f);
    for (int step = 0; step < TP; step++) {
        float2 tcur = make_float2(past[(r0 * TP + step) * 2], past[(r1 * TP + step) * 2]);
        float2 t0 = (step == 0) ? make_float2(tcur.x - 1.f, tcur.y - 1.f) : tprev;
        integrate2(tid, sm, t0, tcur, rb1, rb2a, rb2b, rb3);

        float2 x = make_float2(past[(r0 * TP + step) * 2 + 1],
                               past[(r1 * TP + step) * 2 + 1]);
        const float4* y4 = (const float4*)(sm + OFF_Y);
        for (int jj = tid; jj < 300; jj += NTHR) {
            float bh = __ldg(bhh + jj);
            float a0 = bh, a1 = bh, b0 = 0.f, b1 = 0.f;
#pragma unroll 10
            for (int k = 0; k < 100; k += 2) {
                float w0 = __ldcg(g_WhhT + k * 300 + jj);
                float w1 = __ldcg(g_WhhT + (k + 1) * 300 + jj);
                float4 y = y4[k >> 1];
                a0 = fmaf(w0, y.x, a0); a1 = fmaf(w0, y.y, a1);
                b0 = fmaf(w1, y.z, b0); b1 = fmaf(w1, y.w, b1);
            }
            a0 += b0; a1 += b1;
            float wi = __ldg(Wih + jj), bi = __ldg(bih + jj);
            float2 gi = make_float2(fmaf(wi, x.x, bi), fmaf(wi, x.y, bi));
            if (jj < 200) s_u[jj] = make_float2(gi.x + a0, gi.y + a1);
            else { s_inn[jj - 200] = gi; s_hn[jj - 200] = make_float2(a0, a1); }
        }
        __syncthreads();
        if (tid < HH) {
            float2 u1 = s_u[tid], u2 = s_u[HH + tid];
            float2 gin = s_inn[tid], ghn = s_hn[tid], h = s_y[tid];
            float rx = sigm1(u1.x), ry = sigm1(u1.y);
            float zx = sigm1(u2.x), zy = sigm1(u2.y);
            float nx = tanhf(gin.x + rx * ghn.x), ny = tanhf(gin.y + ry * ghn.y);
            s_y[tid] = make_float2((1.f - zx) * nx + zx * h.x,
                                   (1.f - zy) * ny + zy * h.y);
        }
        __syncthreads();
        tprev = tcur;
    }
    if (tid < HH) {
        g_hB[r0 * HH + tid] = s_y[tid].x;
        g_hB[r1 * HH + tid] = s_y[tid].y;
    }
}

// ---- decoder head ----
__global__ void gx_kernel(const float* __restrict__ gW1, const float* __restrict__ gb1,
                          const float* __restrict__ gW2, const float* __restrict__ gb2,
                          const float* __restrict__ gW3, const float* __restrict__ gb3) {
    int b = blockIdx.x, tid = threadIdx.x;
    __shared__ float sh[HH], s1[HGG], s2[HGG];
    for (int k = tid; k < HH; k += blockDim.x) sh[k] = g_hB[b * HH + k];
    __syncthreads();
    if (tid < HGG) {
        float a = __ldg(gb1 + tid);
        const float* w = gW1 + tid * HH;
        for (int k = 0; k < HH; k++) a = fmaf(__ldg(w + k), sh[k], a);
        s1[tid] = leaky1(a);
    }
    __syncthreads();
    if (tid < HGG) {
        float a = __ldg(gb2 + tid);
        const float* w = gW2 + tid * HGG;
        for (int k = 0; k < HGG; k++) a = fmaf(__ldg(w + k), s1[k], a);
        s2[tid] = leaky1(a);
    }
    __syncthreads();
    if (tid < 2) {
        float a = __ldg(gb3 + tid);
        const float* w = gW3 + tid * HGG;
        for (int k = 0; k < HGG; k++) a = fmaf(__ldg(w + k), s2[k], a);
        g_gx[b * 2 + tid] = a;
    }
}

__global__ void z0_kernel(const float* __restrict__ eps) {
    int b = blockIdx.x, h = threadIdx.x;
    float loc, scale;
    if (b < NB / 2) {
        loc   = g_gx[(2 * b) * 2 + 0];
        scale = g_gx[(2 * b + 1) * 2 + 0];
    } else {
        int i = 2 * (b - NB / 2);
        loc   = fabsf(g_gx[i * 2 + 1]);
        scale = fabsf(g_gx[(i + 1) * 2 + 1]);
    }
    g_z0[b * HH + h] = loc + scale * eps[h * NB + b];
}

// ---- rollout output MLP ----
__device__ __forceinline__ void out_mlp(int tid, int s, int r0, int r1, float* sm,
        float rob1, float rob2,
        const float* __restrict__ oW3, const float* __restrict__ ob3,
        float* __restrict__ out) {
    float2* s_o1 = (float2*)(sm + OFF_HID);
    float2* s_o2 = (float2*)(sm + OFF_A2);
    if (tid < HOO) {
        const float4* y4 = (const float4*)(sm + OFF_Y);
        float a0 = rob1, a1 = rob1, b0 = 0.f, b1 = 0.f;
#pragma unroll 10
        for (int k = 0; k < 100; k += 2) {
            float w0 = __ldcg(g_oW1T + k * 75 + tid);
            float w1 = __ldcg(g_oW1T + (k + 1) * 75 + tid);
            float4 y = y4[k >> 1];
            a0 = fmaf(w0, y.x, a0); a1 = fmaf(w0, y.y, a1);
            b0 = fmaf(w1, y.z, b0); b1 = fmaf(w1, y.w, b1);
        }
        s_o1[tid] = make_float2(leaky1(a0 + b0), leaky1(a1 + b1));
    }
    __syncthreads();
    if (tid < HOO) {
        const float4* h4 = (const float4*)(sm + OFF_HID);
        float a0 = rob2, a1 = rob2, b0 = 0.f, b1 = 0.f;
#pragma unroll 8
        for (int k = 0; k + 1 < HOO; k += 2) {
            float w0 = __ldcg(g_oW2T + k * 75 + tid);
            float w1 = __ldcg(g_oW2T + (k + 1) * 75 + tid);
            float4 h = h4[k >> 1];
            a0 = fmaf(w0, h.x, a0); a1 = fmaf(w0, h.y, a1);
            b0 = fmaf(w1, h.z, b0); b1 = fmaf(w1, h.w, b1);
        }
        {
            float w0 = __ldcg(g_oW2T + 74 * 75 + tid);
            float2 h = s_o1[74];
            a0 = fmaf(w0, h.x, a0); a1 = fmaf(w0, h.y, a1);
        }
        s_o2[tid] = make_float2(leaky1(a0 + b0), leaky1(a1 + b1));
    }
    __syncthreads();
    if (tid < 32) {
        float a0 = 0.f, a1 = 0.f;
        for (int k = tid; k < HOO; k += 32) {
            float wv = __ldg(oW3 + k);
            float2 h = s_o2[k];
            a0 = fmaf(wv, h.x, a0); a1 = fmaf(wv, h.y, a1);
        }
#pragma unroll
        for (int o = 16; o; o >>= 1) {
            a0 += __shfl_down_sync(0xffffffffu, a0, o);
            a1 += __shfl_down_sync(0xffffffffu, a1, o);
        }
        if (tid == 0) {
            float b = __ldg(ob3);
            out[r0 * TFUT + s] = a0 + b;
            out[r1 * TFUT + s] = a1 + b;
        }
    }
    __syncthreads();
}

__global__ void __launch_bounds__(NTHR, 1) rollout_kernel(
        const float* __restrict__ tf_,
        const float* __restrict__ fb1, const float* __restrict__ fb2,
        const float* __restrict__ fb3,
        const float* __restrict__ ob1, const float* __restrict__ ob2,
        const float* __restrict__ oW3, const float* __restrict__ ob3,
        float* __restrict__ out) {
    extern __shared__ float sm[];
    int tid = threadIdx.x;
    int r0 = blockIdx.x * 2, r1 = r0 + 1;

    const float4* src = (const float4*)g_W13P;
    float4* dst = (float4*)sm;
    for (int i = tid; i < 55652 / 4; i += NTHR) dst[i] = src[i];

    float rb1 = (tid < NF) ? __ldg(fb1 + tid) : 0.f;
    int g = tid / 144, j = tid - g * 144;
    float rb2a = 0.f, rb2b = 0.f;
    if (g == 0 && j < 138) {
        rb2a = __ldg(fb2 + 2 * j);
        rb2b = (2 * j + 1 < NF) ? __ldg(fb2 + 2 * j + 1) : 0.f;
    }
    float rb3 = (tid < HH) ? __ldg(fb3 + tid) : 0.f;
    float rob1 = (tid < HOO) ? __ldg(ob1 + tid) : 0.f;
    float rob2 = (tid < HOO) ? __ldg(ob2 + tid) : 0.f;

    float2* s_y = (float2*)(sm + OFF_Y);
    if (tid < HH) s_y[tid] = make_float2(g_z0[r0 * HH + tid], g_z0[r1 * HH + tid]);
    if (tid == 0) {
        ((float2*)(sm + OFF_HID))[275] = make_float2(0.f, 0.f);
        ((float2*)(sm + OFF_IN))[101] = make_float2(0.f, 0.f);
    }
    __syncthreads();

    out_mlp(tid, 0, r0, r1, sm, rob1, rob2, oW3, ob3, out);

    float2 tprev = make_float2(tf_[r0 * TFUT], tf_[r1 * TFUT]);
    for (int s = 1; s < TFUT; s++) {
        float2 tcur = make_float2(tf_[r0 * TFUT + s], tf_[r1 * TFUT + s]);
        integrate2(tid, sm, tprev, tcur, rb1, rb2a, rb2b, rb3);
        out_mlp(tid, s, r0, r1, sm, rob1, rob2, oW3, ob3, out);
        tprev = tcur;
    }
}

extern "C" void kernel_launch(void* const* d_in, const int* in_sizes, int n_in,
                              void* d_out, int out_size) {
    const float* past = (const float*)d_in[0];
    const float* h0   = (const float*)d_in[1];
    const float* t_fu = (const float*)d_in[2];
    const float* eps  = (const float*)d_in[3];
    const float* fW1  = (const float*)d_in[4];
    const float* fb1  = (const float*)d_in[5];
    const float* fW2  = (const float*)d_in[6];
    const float* fb2  = (const float*)d_in[7];
    const float* fW3  = (const float*)d_in[8];
    const float* fb3  = (const float*)d_in[9];
    const float* Wih  = (const float*)d_in[10];
    const float* Whh  = (const float*)d_in[11];
    const float* bih  = (const float*)d_in[12];
    const float* bhh  = (const float*)d_in[13];
    const float* gW1  = (const float*)d_in[14];
    const float* gb1  = (const float*)d_in[15];
    const float* gW2  = (const float*)d_in[16];
    const float* gb2  = (const float*)d_in[17];
    const float* gW3  = (const float*)d_in[18];
    const float* gb3  = (const float*)d_in[19];
    const float* oW1  = (const float*)d_in[20];
    const float* ob1  = (const float*)d_in[21];
    const float* oW2  = (const float*)d_in[22];
    const float* ob2  = (const float*)d_in[23];
    const float* oW3  = (const float*)d_in[24];
    const float* ob3  = (const float*)d_in[25];
    float* out = (float*)d_out;

    static bool attr_done = false;
    if (!attr_done) {
        cudaFuncSetAttribute(encode_kernel,
                             cudaFuncAttributeMaxDynamicSharedMemorySize, SMEM_BYTES);
        cudaFuncSetAttribute(rollout_kernel,
                             cudaFuncAttributeMaxDynamicSharedMemorySize, SMEM_BYTES);
        attr_done = true;
    }

    prep_kernel<<<192, 256>>>(fW1, fW2, fW3, Whh, oW1, oW2);
    encode_kernel<<<NCTA, NTHR, SMEM_BYTES>>>(past, h0, fb1, fb2, fb3, Wih, bih, bhh);
    gx_kernel<<<NB, 96>>>(gW1, gb1, gW2, gb2, gW3, gb3);
    z0_kernel<<<NB, HH>>>(eps);
    rollout_kernel<<<NCTA, NTHR, SMEM_BYTES>>>(t_fu, fb1, fb2, fb3,
                                               ob1, ob2, oW3, ob3, out);
}

// round 13
// speedup vs baseline: 1.7830x; 1.1323x over previous
#include <cuda_runtime.h>
#include <cuda_fp16.h>
#include <math.h>

#define NB    256
#define TP    32
#define TFUT  256
#define HH    100
#define NF    275
#define HGG   75
#define HOO   75
#define NTHR  576
#define NCTA  128

typedef unsigned long long ull;

// ---- weights in global scratch ----
// W1P fp32 paired: W1P[(kp*275+n)*2+r], k=2kp+r, kp 0..51 (k>=101 zero)
__device__ __align__(16) float g_W1P[28600];
// W3 fp16 paired: g_W3H[kp*100+n] = half2(W3[n][2kp], W3[n][2kp+1]), kp 0..139 (k>=275 zero)
__device__ __align__(16) unsigned int g_W3H[14000];
// W2 fp16: g_W2H[k*138+j] = half2(W2[2j][k], W2[2j+1][k]); k 0..275 (row 275 zero)
__device__ __align__(16) __half2 g_W2H[276 * 138];
__device__ __align__(16) float g_WhhT[100 * 300];
__device__ __align__(16) float g_oW1T[100 * 75];
__device__ __align__(16) float g_oW2T[75 * 75];
__device__ float g_hB[NB * HH];
__device__ float g_gx[NB * 2];
__device__ float g_z0[NB * HH];

// ---- shared layout (float offsets), total 45976 floats = 183,904 B ----
#define OFF_W1P  0        // 28600 floats
#define OFF_W3H  28600    // 14000 uints
#define OFF_IN   42600    // float2[104] (101..103 zero)
#define OFF_HID  42808    // float2[276] (275 zero)
#define OFF_A2   43360    // float2[280] (276..279 zero)
#define OFF_Y    43920    // float2[100]
#define OFF_KS   44120    // float2[100]
#define OFF_PART 44320    // 1656 floats scratch
#define SMEM_BYTES (45976 * 4)

__device__ __forceinline__ float leaky1(float x) {
    const float SL = 1.0f / 5.5f;
    return x >= 0.f ? x : x * SL;
}
__device__ __forceinline__ float sigm1(float x) { return 1.f / (1.f + expf(-x)); }

// ---- packed fp32x2 FMA ----
#define FMA_X2(ACC, W, X) \
    asm("fma.rn.f32x2 %0, %1, %2, %0;" : "+l"(ACC) : "l"(W), "l"(X))

#define W2REFILL16(R, ROW0) {                                                 \
    _Pragma("unroll")                                                         \
    for (int i_ = 0; i_ < 16; i_++)                                           \
        R[i_] = __ldcg((const unsigned int*)(ph + ((ROW0) + i_) * 138)); }

#define W2CONS16(R, OFF) {                                                    \
    _Pragma("unroll")                                                         \
    for (int ii_ = 0; ii_ < 16; ii_++) {                                      \
        float2 wf_ = __half22float2(*(const __half2*)&R[ii_]);                \
        ull wa_, wb_, xv_ = xu[(OFF) + ii_];                                  \
        asm("mov.b64 %0, {%1, %1};" : "=l"(wa_) : "f"(wf_.x));                \
        asm("mov.b64 %0, {%1, %1};" : "=l"(wb_) : "f"(wf_.y));                \
        if (ii_ & 1) { FMA_X2(acA2, wa_, xv_); FMA_X2(acB2, wb_, xv_); }      \
        else         { FMA_X2(acA,  wa_, xv_); FMA_X2(acB,  wb_, xv_); }      \
    } }

// ---- One RK4 stage: 576-thread field MLP with 2/4/4-way k-splits ----
__device__ __forceinline__ void field_stage(int tid, float* sm, int stage,
        float2 dt, float2 tnext, bool write_in,
        float rb1, float rb2a, float rb2b, float rb3) {
    float2* s_in  = (float2*)(sm + OFF_IN);
    float2* s_hid = (float2*)(sm + OFF_HID);
    float2* s_a2  = (float2*)(sm + OFF_A2);
    float2* s_y   = (float2*)(sm + OFF_Y);
    float2* s_ks  = (float2*)(sm + OFF_KS);
    float2* s_l1p = (float2*)(sm + OFF_PART);   // float2[275]
    float4* s_p4  = (float4*)(sm + OFF_PART);   // float4[414]
    float2* s_l3p = (float2*)(sm + OFF_PART);   // float2[300]

    int q = tid / 138, j = tid - q * 138;       // L2/L3 split
    bool actL2 = (q < 4);
    const __half2* ph = g_W2H + (q * 69) * 138 + j;

    // ---- W2 prefetch (rows 0..31 + tail 64..68) issued before L1 ----
    unsigned int A[16], B[16], T[5];
    if (actL2) {
        W2REFILL16(A, 0)
        W2REFILL16(B, 16)
#pragma unroll
        for (int i = 0; i < 5; i++)
            T[i] = __ldcg((const unsigned int*)(ph + (64 + i) * 138));
    }

    // ---- L1: 101 -> 275, k-split 2 ways (26 kp each; kp 51 is zero pad) ----
    int h = tid / 275, n = tid - h * 275;
    float2 l1acc = make_float2(0.f, 0.f);
    if (tid < 550) {
        const float2* wp = ((const float2*)(sm + OFF_W1P)) + n;
        const float4* x4 = (const float4*)(sm + OFF_IN);
        int kp0 = h * 26;
        float a0 = 0.f, a1 = 0.f, b0 = 0.f, b1 = 0.f;
#pragma unroll
        for (int u = 0; u < 26; u++) {
            float2 w = wp[(kp0 + u) * 275];
            float4 x = x4[kp0 + u];
            a0 = fmaf(w.x, x.x, a0); a1 = fmaf(w.x, x.y, a1);
            b0 = fmaf(w.y, x.z, b0); b1 = fmaf(w.y, x.w, b1);
        }
        l1acc = make_float2(a0 + b0, a1 + b1);
        if (h) s_l1p[n] = l1acc;
    }
    __syncthreads();
    if (tid < 275) {
        float2 p = s_l1p[tid];
        s_hid[tid] = make_float2(tanhf(l1acc.x + p.x + rb1),
                                 tanhf(l1acc.y + p.y + rb1));
    }
    __syncthreads();

    // ---- L2: 275 -> 275, fp16 weights, FMA2, k-split 4 ways (69 rows each) ----
    float4 acc = make_float4(0.f, 0.f, 0.f, 0.f);
    if (actL2) {
        const ull* xu = (const ull*)(((const float2*)(sm + OFF_HID)) + q * 69);
        ull acA = 0ull, acA2 = 0ull, acB = 0ull, acB2 = 0ull;
        W2CONS16(A, 0)  W2REFILL16(A, 32)
        W2CONS16(B, 16) W2REFILL16(B, 48)
        W2CONS16(A, 32)
#pragma unroll
        for (int i = 0; i < 5; i++) {        // tail rows 64..68
            float2 wf = __half22float2(*(const __half2*)&T[i]);
            ull wa, wb, xv = xu[64 + i];
            asm("mov.b64 %0, {%1, %1};" : "=l"(wa) : "f"(wf.x));
            asm("mov.b64 %0, {%1, %1};" : "=l"(wb) : "f"(wf.y));
            if (i & 1) { FMA_X2(acA2, wa, xv); FMA_X2(acB2, wb, xv); }
            else       { FMA_X2(acA,  wa, xv); FMA_X2(acB,  wb, xv); }
        }
        W2CONS16(B, 48)
        ull sA, sB;
        asm("add.rn.f32x2 %0, %1, %2;" : "=l"(sA) : "l"(acA), "l"(acA2));
        asm("add.rn.f32x2 %0, %1, %2;" : "=l"(sB) : "l"(acB), "l"(acB2));
        float2 fA = *(float2*)&sA, fB = *(float2*)&sB;
        acc = make_float4(fA.x, fA.y, fB.x, fB.y);
        if (q) s_p4[(q - 1) * 138 + j] = acc;
    }
    __syncthreads();
    if (q == 0) {   // tid < 138
        float4 p1 = s_p4[j], p2 = s_p4[138 + j], p3 = s_p4[276 + j];
        float v0 = acc.x + p1.x + p2.x + p3.x + rb2a;
        float v1 = acc.y + p1.y + p2.y + p3.y + rb2a;
        float v2 = acc.z + p1.z + p2.z + p3.z + rb2b;
        float v3 = acc.w + p1.w + p2.w + p3.w + rb2b;
        s_a2[2 * j]     = make_float2(tanhf(v0), tanhf(v1));
        s_a2[2 * j + 1] = make_float2(tanhf(v2), tanhf(v3));
    }
    __syncthreads();

    // ---- L3: 275 -> 100, fp16 W3 in smem, k-split 4 ways (35 kp each) ----
    float2 l3acc = make_float2(0.f, 0.f);
    bool actL3 = actL2 && (j < 100);
    if (actL3) {
        const unsigned int* w3 = ((const unsigned int*)(sm + OFF_W3H)) + j;
        const float4* x4 = (const float4*)(sm + OFF_A2);
        int kp0 = q * 35;
        float a0 = 0.f, a1 = 0.f, b0 = 0.f, b1 = 0.f;
#pragma unroll
        for (int u = 0; u < 35; u++) {
            unsigned int wu = w3[(kp0 + u) * 100];
            float2 wf = __half22float2(*(const __half2*)&wu);
            float4 x = x4[kp0 + u];
            a0 = fmaf(wf.x, x.x, a0); a1 = fmaf(wf.x, x.y, a1);
            b0 = fmaf(wf.y, x.z, b0); b1 = fmaf(wf.y, x.w, b1);
        }
        l3acc = make_float2(a0 + b0, a1 + b1);
        if (q) s_l3p[(q - 1) * 100 + j] = l3acc;
    }
    __syncthreads();
    if (tid < 100) {
        float2 p1 = s_l3p[tid], p2 = s_l3p[100 + tid], p3 = s_l3p[200 + tid];
        float2 f = make_float2(tanhf(l3acc.x + p1.x + p2.x + p3.x + rb3),
                               tanhf(l3acc.y + p1.y + p2.y + p3.y + rb3));
        float2 y = s_y[tid];
        if (stage == 0) {
            s_ks[tid] = f;
            s_in[1 + tid] = make_float2(fmaf(0.5f * dt.x, f.x, y.x),
                                        fmaf(0.5f * dt.y, f.y, y.y));
        } else if (stage == 1) {
            float2 k = s_ks[tid];
            s_ks[tid] = make_float2(k.x + 2.f * f.x, k.y + 2.f * f.y);
            s_in[1 + tid] = make_float2(fmaf(0.5f * dt.x, f.x, y.x),
                                        fmaf(0.5f * dt.y, f.y, y.y));
        } else if (stage == 2) {
            float2 k = s_ks[tid];
            s_ks[tid] = make_float2(k.x + 2.f * f.x, k.y + 2.f * f.y);
            s_in[1 + tid] = make_float2(fmaf(dt.x, f.x, y.x),
                                        fmaf(dt.y, f.y, y.y));
        } else {
            float2 k = s_ks[tid];
            float2 yn = make_float2(y.x + dt.x * (k.x + f.x) / 6.f,
                                    y.y + dt.y * (k.y + f.y) / 6.f);
            s_y[tid] = yn;
            if (write_in) s_in[1 + tid] = yn;
        }
        if (tid == 0 && (stage < 3 || write_in)) s_in[0] = tnext;
    }
    __syncthreads();
}

// ---- RK4, NSUB=2 ----
__device__ __forceinline__ void integrate2(int tid, float* sm, float2 t0, float2 t1,
        float rb1, float rb2a, float rb2b, float rb3) {
    float2* s_in = (float2*)(sm + OFF_IN);
    float2* s_y  = (float2*)(sm + OFF_Y);
    float2 dt = make_float2((t1.x - t0.x) * 0.5f, (t1.y - t0.y) * 0.5f);
    if (tid < HH) s_in[1 + tid] = s_y[tid];
    if (tid == 0) s_in[0] = t0;
    __syncthreads();
#pragma unroll 1
    for (int st = 0; st < 8; st++) {
        int stage = st & 3, sub = st >> 2;
        float2 tb = make_float2(t0.x + sub * dt.x, t0.y + sub * dt.y);
        float2 tnext = (stage <= 1)
            ? make_float2(tb.x + 0.5f * dt.x, tb.y + 0.5f * dt.y)
            : make_float2(tb.x + dt.x, tb.y + dt.y);
        field_stage(tid, sm, stage, dt, tnext, (st == 3), rb1, rb2a, rb2b, rb3);
    }
}

// ---- shared init common to encode/rollout ----
__device__ __forceinline__ void load_shared_weights(int tid, float* sm) {
    const float4* s1 = (const float4*)g_W1P;
    float4* d1 = (float4*)sm;
    for (int i = tid; i < 28600 / 4; i += NTHR) d1[i] = s1[i];
    const uint4* s2 = (const uint4*)g_W3H;
    uint4* d2 = (uint4*)(sm + OFF_W3H);
    for (int i = tid; i < 14000 / 4; i += NTHR) d2[i] = s2[i];
    if (tid == 0) {
        float2* s_in  = (float2*)(sm + OFF_IN);
        float2* s_hid = (float2*)(sm + OFF_HID);
        float2* s_a2  = (float2*)(sm + OFF_A2);
        s_in[101] = s_in[102] = s_in[103] = make_float2(0.f, 0.f);
        s_hid[275] = make_float2(0.f, 0.f);
        s_a2[276] = s_a2[277] = s_a2[278] = s_a2[279] = make_float2(0.f, 0.f);
    }
}

// ---- prep: build packed/transposed weight copies ----
__global__ void prep_kernel(const float* __restrict__ fW1, const float* __restrict__ fW2,
                            const float* __restrict__ fW3, const float* __restrict__ Whh,
                            const float* __restrict__ oW1, const float* __restrict__ oW2) {
    for (int i = blockIdx.x * blockDim.x + threadIdx.x; i < 123813;
         i += gridDim.x * blockDim.x) {
        if (i < 28600) {
            int qq = i >> 1, r = i & 1;
            int kp = qq / 275, n = qq % 275;
            int k = 2 * kp + r;
            g_W1P[i] = (k < 101) ? fW1[n * 101 + k] : 0.f;
        } else if (i < 42600) {
            int idx = i - 28600;
            int kp = idx / 100, n = idx % 100;
            int k0 = 2 * kp, k1 = 2 * kp + 1;
            float v0 = (k0 < 275) ? fW3[n * 275 + k0] : 0.f;
            float v1 = (k1 < 275) ? fW3[n * 275 + k1] : 0.f;
            __half2 hv = __floats2half2_rn(v0, v1);
            g_W3H[idx] = *(unsigned int*)&hv;
        } else if (i < 80688) {
            int idx = i - 42600;
            int k = idx / 138, jj = idx % 138;
            int n0 = 2 * jj, n1 = 2 * jj + 1;
            float v0 = (k < 275) ? fW2[n0 * 275 + k] : 0.f;
            float v1 = (k < 275 && n1 < 275) ? fW2[n1 * 275 + k] : 0.f;
            g_W2H[idx] = __floats2half2_rn(v0, v1);
        } else if (i < 110688) {
            int jj = i - 80688, k = jj / 300, n = jj % 300;
            g_WhhT[jj] = Whh[n * 100 + k];
        } else if (i < 118188) {
            int jj = i - 110688, k = jj / 75, n = jj % 75;
            g_oW1T[jj] = oW1[n * 100 + k];
        } else {
            int jj = i - 118188, k = jj / 75, n = jj % 75;
            g_oW2T[jj] = oW2[n * 75 + k];
        }
    }
}

// ---- encode ----
__global__ void __launch_bounds__(NTHR, 1) encode_kernel(
        const float* __restrict__ past, const float* __restrict__ h0,
        const float* __restrict__ fb1, const float* __restrict__ fb2,
        const float* __restrict__ fb3,
        const float* __restrict__ Wih, const float* __restrict__ bih,
        const float* __restrict__ bhh) {
    extern __shared__ float sm[];
    int tid = threadIdx.x;
    int r0 = blockIdx.x * 2, r1 = r0 + 1;

    load_shared_weights(tid, sm);

    float rb1 = (tid < NF) ? __ldg(fb1 + tid) : 0.f;
    float rb2a = 0.f, rb2b = 0.f;
    if (tid < 138) {
        rb2a = __ldg(fb2 + 2 * tid);
        rb2b = (2 * tid + 1 < NF) ? __ldg(fb2 + 2 * tid + 1) : 0.f;
    }
    float rb3 = (tid < HH) ? __ldg(fb3 + tid) : 0.f;

    float2* s_y   = (float2*)(sm + OFF_Y);
    float2* s_u   = (float2*)(sm + OFF_HID);   // [200] aliased
    float2* s_inn = (float2*)(sm + OFF_A2);    // [100]
    float2* s_hn  = (float2*)(sm + OFF_PART);  // [100]
    if (tid < HH) s_y[tid] = make_float2(h0[r0 * HH + tid], h0[r1 * HH + tid]);
    __syncthreads();

    float2 tprev = make_float2(0.f, 0.f);
    for (int step = 0; step < TP; step++) {
        float2 tcur = make_float2(past[(r0 * TP + step) * 2], past[(r1 * TP + step) * 2]);
        float2 t0 = (step == 0) ? make_float2(tcur.x - 1.f, tcur.y - 1.f) : tprev;
        integrate2(tid, sm, t0, tcur, rb1, rb2a, rb2b, rb3);

        float2 x = make_float2(past[(r0 * TP + step) * 2 + 1],
                               past[(r1 * TP + step) * 2 + 1]);
        const float4* y4 = (const float4*)(sm + OFF_Y);
        if (tid < 300) {
            int jj = tid;
            float bh = __ldg(bhh + jj);
            float a0 = bh, a1 = bh, b0 = 0.f, b1 = 0.f;
#pragma unroll 10
            for (int k = 0; k < 100; k += 2) {
                float w0 = __ldcg(g_WhhT + k * 300 + jj);
                float w1 = __ldcg(g_WhhT + (k + 1) * 300 + jj);
                float4 y = y4[k >> 1];
                a0 = fmaf(w0, y.x, a0); a1 = fmaf(w0, y.y, a1);
                b0 = fmaf(w1, y.z, b0); b1 = fmaf(w1, y.w, b1);
            }
            a0 += b0; a1 += b1;
            float wi = __ldg(Wih + jj), bi = __ldg(bih + jj);
            float2 gi = make_float2(fmaf(wi, x.x, bi), fmaf(wi, x.y, bi));
            if (jj < 200) s_u[jj] = make_float2(gi.x + a0, gi.y + a1);
            else { s_inn[jj - 200] = gi; s_hn[jj - 200] = make_float2(a0, a1); }
        }
        __syncthreads();
        if (tid < HH) {
            float2 u1 = s_u[tid], u2 = s_u[HH + tid];
            float2 gin = s_inn[tid], ghn = s_hn[tid], hcur = s_y[tid];
            float rx = sigm1(u1.x), ry = sigm1(u1.y);
            float zx = sigm1(u2.x), zy = sigm1(u2.y);
            float nx = tanhf(gin.x + rx * ghn.x), ny = tanhf(gin.y + ry * ghn.y);
            s_y[tid] = make_float2((1.f - zx) * nx + zx * hcur.x,
                                   (1.f - zy) * ny + zy * hcur.y);
        }
        __syncthreads();
        tprev = tcur;
    }
    if (tid < HH) {
        g_hB[r0 * HH + tid] = s_y[tid].x;
        g_hB[r1 * HH + tid] = s_y[tid].y;
    }
}

// ---- decoder head ----
__global__ void gx_kernel(const float* __restrict__ gW1, const float* __restrict__ gb1,
                          const float* __restrict__ gW2, const float* __restrict__ gb2,
                          const float* __restrict__ gW3, const float* __restrict__ gb3) {
    int b = blockIdx.x, tid = threadIdx.x;
    __shared__ float sh[HH], s1[HGG], s2[HGG];
    for (int k = tid; k < HH; k += blockDim.x) sh[k] = g_hB[b * HH + k];
    __syncthreads();
    if (tid < HGG) {
        float a = __ldg(gb1 + tid);
        const float* w = gW1 + tid * HH;
        for (int k = 0; k < HH; k++) a = fmaf(__ldg(w + k), sh[k], a);
        s1[tid] = leaky1(a);
    }
    __syncthreads();
    if (tid < HGG) {
        float a = __ldg(gb2 + tid);
        const float* w = gW2 + tid * HGG;
        for (int k = 0; k < HGG; k++) a = fmaf(__ldg(w + k), s1[k], a);
        s2[tid] = leaky1(a);
    }
    __syncthreads();
    if (tid < 2) {
        float a = __ldg(gb3 + tid);
        const float* w = gW3 + tid * HGG;
        for (int k = 0; k < HGG; k++) a = fmaf(__ldg(w + k), s2[k], a);
        g_gx[b * 2 + tid] = a;
    }
}

__global__ void z0_kernel(const float* __restrict__ eps) {
    int b = blockIdx.x, h = threadIdx.x;
    float loc, scale;
    if (b < NB / 2) {
        loc   = g_gx[(2 * b) * 2 + 0];
        scale = g_gx[(2 * b + 1) * 2 + 0];
    } else {
        int i = 2 * (b - NB / 2);
        loc   = fabsf(g_gx[i * 2 + 1]);
        scale = fabsf(g_gx[(i + 1) * 2 + 1]);
    }
    g_z0[b * HH + h] = loc + scale * eps[h * NB + b];
}

// ---- rollout output MLP ----
__device__ __forceinline__ void out_mlp(int tid, int s, int r0, int r1, float* sm,
        float rob1, float rob2,
        const float* __restrict__ oW3, const float* __restrict__ ob3,
        float* __restrict__ out) {
    float2* s_o1 = (float2*)(sm + OFF_HID);
    float2* s_o2 = (float2*)(sm + OFF_A2);
    if (tid < HOO) {
        const float4* y4 = (const float4*)(sm + OFF_Y);
        float a0 = rob1, a1 = rob1, b0 = 0.f, b1 = 0.f;
#pragma unroll 10
        for (int k = 0; k < 100; k += 2) {
            float w0 = __ldcg(g_oW1T + k * 75 + tid);
            float w1 = __ldcg(g_oW1T + (k + 1) * 75 + tid);
            float4 y = y4[k >> 1];
            a0 = fmaf(w0, y.x, a0); a1 = fmaf(w0, y.y, a1);
            b0 = fmaf(w1, y.z, b0); b1 = fmaf(w1, y.w, b1);
        }
        s_o1[tid] = make_float2(leaky1(a0 + b0), leaky1(a1 + b1));
    }
    __syncthreads();
    if (tid < HOO) {
        const float4* h4 = (const float4*)(sm + OFF_HID);
        float a0 = rob2, a1 = rob2, b0 = 0.f, b1 = 0.f;
#pragma unroll 8
        for (int k = 0; k + 1 < HOO; k += 2) {
            float w0 = __ldcg(g_oW2T + k * 75 + tid);
            float w1 = __ldcg(g_oW2T + (k + 1) * 75 + tid);
            float4 h = h4[k >> 1];
            a0 = fmaf(w0, h.x, a0); a1 = fmaf(w0, h.y, a1);
            b0 = fmaf(w1, h.z, b0); b1 = fmaf(w1, h.w, b1);
        }
        {
            float w0 = __ldcg(g_oW2T + 74 * 75 + tid);
            float2 h = s_o1[74];
            a0 = fmaf(w0, h.x, a0); a1 = fmaf(w0, h.y, a1);
        }
        s_o2[tid] = make_float2(leaky1(a0 + b0), leaky1(a1 + b1));
    }
    __syncthreads();
    if (tid < 32) {
        float a0 = 0.f, a1 = 0.f;
        for (int k = tid; k < HOO; k += 32) {
            float wv = __ldg(oW3 + k);
            float2 h = s_o2[k];
            a0 = fmaf(wv, h.x, a0); a1 = fmaf(wv, h.y, a1);
        }
#pragma unroll
        for (int o = 16; o; o >>= 1) {
            a0 += __shfl_down_sync(0xffffffffu, a0, o);
            a1 += __shfl_down_sync(0xffffffffu, a1, o);
        }
        if (tid == 0) {
            float b = __ldg(ob3);
            out[r0 * TFUT + s] = a0 + b;
            out[r1 * TFUT + s] = a1 + b;
        }
    }
    __syncthreads();
}

__global__ void __launch_bounds__(NTHR, 1) rollout_kernel(
        const float* __restrict__ tf_,
        const float* __restrict__ fb1, const float* __restrict__ fb2,
        const float* __restrict__ fb3,
        const float* __restrict__ ob1, const float* __restrict__ ob2,
        const float* __restrict__ oW3, const float* __restrict__ ob3,
        float* __restrict__ out) {
    extern __shared__ float sm[];
    int tid = threadIdx.x;
    int r0 = blockIdx.x * 2, r1 = r0 + 1;

    load_shared_weights(tid, sm);

    float rb1 = (tid < NF) ? __ldg(fb1 + tid) : 0.f;
    float rb2a = 0.f, rb2b = 0.f;
    if (tid < 138) {
        rb2a = __ldg(fb2 + 2 * tid);
        rb2b = (2 * tid + 1 < NF) ? __ldg(fb2 + 2 * tid + 1) : 0.f;
    }
    float rb3 = (tid < HH) ? __ldg(fb3 + tid) : 0.f;
    float rob1 = (tid < HOO) ? __ldg(ob1 + tid) : 0.f;
    float rob2 = (tid < HOO) ? __ldg(ob2 + tid) : 0.f;

    float2* s_y = (float2*)(sm + OFF_Y);
    if (tid < HH) s_y[tid] = make_float2(g_z0[r0 * HH + tid], g_z0[r1 * HH + tid]);
    __syncthreads();

    out_mlp(tid, 0, r0, r1, sm, rob1, rob2, oW3, ob3, out);

    float2 tprev = make_float2(tf_[r0 * TFUT], tf_[r1 * TFUT]);
    for (int s = 1; s < TFUT; s++) {
        float2 tcur = make_float2(tf_[r0 * TFUT + s], tf_[r1 * TFUT + s]);
        integrate2(tid, sm, tprev, tcur, rb1, rb2a, rb2b, rb3);
        out_mlp(tid, s, r0, r1, sm, rob1, rob2, oW3, ob3, out);
        tprev = tcur;
    }
}

extern "C" void kernel_launch(void* const* d_in, const int* in_sizes, int n_in,
                              void* d_out, int out_size) {
    const float* past = (const float*)d_in[0];
    const float* h0   = (const float*)d_in[1];
    const float* t_fu = (const float*)d_in[2];
    const float* eps  = (const float*)d_in[3];
    const float* fW1  = (const float*)d_in[4];
    const float* fb1  = (const float*)d_in[5];
    const float* fW2  = (const float*)d_in[6];
    const float* fb2  = (const float*)d_in[7];
    const float* fW3  = (const float*)d_in[8];
    const float* fb3  = (const float*)d_in[9];
    const float* Wih  = (const float*)d_in[10];
    const float* Whh  = (const float*)d_in[11];
    const float* bih  = (const float*)d_in[12];
    const float* bhh  = (const float*)d_in[13];
    const float* gW1  = (const float*)d_in[14];
    const float* gb1  = (const float*)d_in[15];
    const float* gW2  = (const float*)d_in[16];
    const float* gb2  = (const float*)d_in[17];
    const float* gW3  = (const float*)d_in[18];
    const float* gb3  = (const float*)d_in[19];
    const float* oW1  = (const float*)d_in[20];
    const float* ob1  = (const float*)d_in[21];
    const float* oW2  = (const float*)d_in[22];
    const float* ob2  = (const float*)d_in[23];
    const float* oW3  = (const float*)d_in[24];
    const float* ob3  = (const float*)d_in[25];
    float* out = (float*)d_out;

    static bool attr_done = false;
    if (!attr_done) {
        cudaFuncSetAttribute(encode_kernel,
                             cudaFuncAttributeMaxDynamicSharedMemorySize, SMEM_BYTES);
        cudaFuncSetAttribute(rollout_kernel,
                             cudaFuncAttributeMaxDynamicSharedMemorySize, SMEM_BYTES);
        attr_done = true;
    }

    prep_kernel<<<192, 256>>>(fW1, fW2, fW3, Whh, oW1, oW2);
    encode_kernel<<<NCTA, NTHR, SMEM_BYTES>>>(past, h0, fb1, fb2, fb3, Wih, bih, bhh);
    gx_kernel<<<NB, 96>>>(gW1, gb1, gW2, gb2, gW3, gb3);
    z0_kernel<<<NB, HH>>>(eps);
    rollout_kernel<<<NCTA, NTHR, SMEM_BYTES>>>(t_fu, fb1, fb2, fb3,
                                               ob1, ob2, oW3, ob3, out);
}